// round 13
// baseline (speedup 1.0000x reference)
#include <cuda_runtime.h>
#include <cuda_fp16.h>
#include <math.h>

// Problem constants
#define BB   2
#define SS   2048
#define DD   128
#define NN   2048
#define MM   (BB * SS)          // 4096 rows
#define NCH  256                // scan chunks
#define LCH  8                  // steps per chunk (NCH*LCH == SS)

// ---------------- scratch (static device globals; no allocations) ----------------
__device__ __half g_xh[MM * DD], g_xl[MM * DD];                  // fp16 split x
__device__ __half g_Wh[3 * NN * DD], g_Wl[3 * NN * DD];          // fp16 split [W_B; W_C; W_dt]
__device__ __half g_Woh[DD * NN], g_Wol[DD * NN];                // fp16 split W_out
__device__ float  g_abar[MM * NN];                               // exp(dt*A)   (fp32: scan-critical)
__device__ __half g_bbar2[MM * NN];                              // dt*B_feat   (fp16)
__device__ __half g_cf2  [MM * NN];                              // C_feat      (fp16)
__device__ __half g_y[MM * NN];                                  // y = c*h     (single fp16)
__device__ float g_Aprod [BB * NCH * NN];
__device__ float g_Hend  [BB * NCH * NN];
__device__ float g_Hstart[BB * NCH * NN];
__device__ float g_part[4 * MM * DD];                            // split-K partials

// ---------------- helpers ----------------
__device__ __forceinline__ void f16_split(float v, __half& h, __half& l) {
    h = __float2half_rn(v);
    l = __float2half_rn(v - __half2float(h));
}

__device__ __forceinline__ void mma_f16(float* c, const unsigned* a, const unsigned* b) {
    asm volatile(
        "mma.sync.aligned.m16n8k16.row.col.f32.f16.f16.f32 "
        "{%0,%1,%2,%3}, {%4,%5,%6,%7}, {%8,%9}, {%0,%1,%2,%3};\n"
        : "+f"(c[0]), "+f"(c[1]), "+f"(c[2]), "+f"(c[3])
        : "r"(a[0]), "r"(a[1]), "r"(a[2]), "r"(a[3]),
          "r"(b[0]), "r"(b[1]));
}

__device__ __forceinline__ void ldsm4(unsigned* r, const void* p) {
    unsigned a = (unsigned)__cvta_generic_to_shared(p);
    asm volatile("ldmatrix.sync.aligned.m8n8.x4.shared.b16 {%0,%1,%2,%3}, [%4];"
                 : "=r"(r[0]), "=r"(r[1]), "=r"(r[2]), "=r"(r[3]) : "r"(a));
}

__device__ __forceinline__ void cp16(void* smem_dst, const void* gmem_src) {
    unsigned s = (unsigned)__cvta_generic_to_shared(smem_dst);
    asm volatile("cp.async.cg.shared.global [%0], [%1], 16;\n" :: "r"(s), "l"(gmem_src));
}
#define CP_COMMIT() asm volatile("cp.async.commit_group;\n" ::: "memory")
#define CP_WAIT1()  asm volatile("cp.async.wait_group 1;\n" ::: "memory")

// ---------------- 0) split inputs into fp16 hi/lo (x4 vectorized) ----------------
__global__ void split_kernel(const float* __restrict__ x,
                             const float* __restrict__ WB,
                             const float* __restrict__ WC,
                             const float* __restrict__ Wdt,
                             const float* __restrict__ Wout) {
    const int XE  = MM * DD;        // 524288
    const int WE  = NN * DD;        // 262144 per matrix
    const int WOE = DD * NN;        // 262144
    int i4 = (blockIdx.x * blockDim.x + threadIdx.x) * 4;

    const float* src;
    __half *dh, *dl;
    int off;
    if (i4 < XE) {
        src = x; off = i4; dh = g_xh; dl = g_xl;
    } else if (i4 < XE + 3 * WE) {
        int j = i4 - XE;
        src = (j < WE) ? WB : ((j < 2 * WE) ? WC : Wdt);
        off = j % WE; dh = g_Wh + (j - off); dl = g_Wl + (j - off);
    } else if (i4 < XE + 3 * WE + WOE) {
        int j = i4 - XE - 3 * WE;
        src = Wout; off = j; dh = g_Woh; dl = g_Wol;
    } else return;

    float4 v = *(const float4*)&src[off];
    __half h0, l0, h1, l1, h2, l2, h3, l3;
    f16_split(v.x, h0, l0); f16_split(v.y, h1, l1);
    f16_split(v.z, h2, l2); f16_split(v.w, h3, l3);
    union { __half2 b2[2]; uint2 u; } uh, ul;
    uh.b2[0] = __halves2half2(h0, h1); uh.b2[1] = __halves2half2(h2, h3);
    ul.b2[0] = __halves2half2(l0, l1); ul.b2[1] = __halves2half2(l2, l3);
    *(uint2*)&dh[off] = uh.u;
    *(uint2*)&dl[off] = ul.u;
}

// ---------------- 1) fused projection GEMM + featurizer + chunk-scan pass 1 -------
// Block tile: 128 (m) x 64 (n) per matrix, 512 threads (warps 4m x 4n), 1 CTA/SM.
// K=128 in 4 chunks of 32, cp.async double-buffered.
// fp16 2-split. Passes: hh only for W_B/W_C; (hh, hl, lh) for W_dt (scan-critical).
// An m-block = 16 scan chunks (LCH=8); scan pass-1 runs in-CTA from the smem stage.
#define G1_SX_ELEMS (2*2*128*40)         // [buf][sel][row][pitch40] shorts
#define G1_SW_ELEMS (2*4*64*40)          // [buf][combo][row][pitch40] shorts
#define G1_TILES ((G1_SX_ELEMS + G1_SW_ELEMS) * 2)          // 81,920 B
#define G1_STAGE (3*128*66*4 + 4*64*4)                      // 102,400 B
#define G1_SMEM  (G1_STAGE > G1_TILES ? G1_STAGE : G1_TILES)

__global__ __launch_bounds__(512, 1)
void gemm1_proj(const float* __restrict__ bB, const float* __restrict__ bC,
                const float* __restrict__ bdt, const float* __restrict__ Alog) {
    extern __shared__ unsigned short smem_u16[];
    typedef unsigned short (*SXt)[2][128][40];
    typedef unsigned short (*SWt)[4][64][40];
    SXt sX = (SXt)smem_u16;
    SWt sW = (SWt)(smem_u16 + G1_SX_ELEMS);

    const int tid  = threadIdx.x;
    const int warp = tid >> 5, lane = tid & 31;
    const int wm = warp >> 2, wn = warp & 3;
    const int m0 = blockIdx.y * 128;
    const int n0 = blockIdx.x * 64;
    const int g  = lane >> 2, tg = lane & 3;
    const int lm = lane >> 3, lr = lane & 7;     // ldmatrix lane decomposition

    float acc[3][2][2][4];
    #pragma unroll
    for (int a = 0; a < 3; a++)
        #pragma unroll
        for (int b = 0; b < 2; b++)
            #pragma unroll
            for (int c = 0; c < 2; c++)
                #pragma unroll
                for (int d = 0; d < 4; d++) acc[a][b][c][d] = 0.f;

    // async tile loader for k-chunk kc into buffer buf
    // W combos: 0=(B,h) 1=(C,h) 2=(dt,h) 3=(dt,l)
    auto load_tiles = [&](int buf, int kc) {
        #pragma unroll
        for (int j = 0; j < 2; j++) {               // x: 1024 x 16B
            int i = tid + j * 512;
            int sel = i >> 9, r = (i >> 2) & 127, w = i & 3;
            const __half* src = (sel ? g_xl : g_xh) + (m0 + r) * DD + kc * 32 + w * 8;
            cp16(&sX[buf][sel][r][w * 8], src);
        }
        #pragma unroll
        for (int j = 0; j < 2; j++) {               // W: 1024 x 16B
            int i = tid + j * 512;
            int combo = i >> 8, r = (i >> 2) & 63, w = i & 3;
            int mat = (combo < 3) ? combo : 2;
            const __half* src = ((combo == 3) ? g_Wl : g_Wh) + (mat * NN + n0 + r) * DD + kc * 32 + w * 8;
            cp16(&sW[buf][combo][r][w * 8], src);
        }
    };

    load_tiles(0, 0);
    CP_COMMIT();

    for (int kc = 0; kc < 4; kc++) {
        if (kc < 3) load_tiles((kc + 1) & 1, kc + 1);
        CP_COMMIT();                 // real group, or empty group on last iter
        CP_WAIT1();                  // forces chunk-kc group completion
        __syncthreads();
        const int buf = kc & 1;

        #pragma unroll
        for (int ks = 0; ks < 2; ks++) {
            const int kb = ks * 16;
            // hoisted A fragments: [sel][mt][4 regs]  (4 LDSM)
            unsigned afr[2][2][4];
            #pragma unroll
            for (int as = 0; as < 2; as++)
                #pragma unroll
                for (int mt = 0; mt < 2; mt++)
                    ldsm4(afr[as][mt],
                          &sX[buf][as][wm * 32 + mt * 16 + (lm & 1) * 8 + lr][kb + (lm >> 1) * 8]);
            // hoisted B fragments (4 LDSM): B.h, C.h, dt.h, dt.l
            unsigned bfrB[4], bfrC[4], bfrD[2][4];
            ldsm4(bfrB,    &sW[buf][0][wn * 16 + (lm >> 1) * 8 + lr][kb + (lm & 1) * 8]);
            ldsm4(bfrC,    &sW[buf][1][wn * 16 + (lm >> 1) * 8 + lr][kb + (lm & 1) * 8]);
            ldsm4(bfrD[0], &sW[buf][2][wn * 16 + (lm >> 1) * 8 + lr][kb + (lm & 1) * 8]);
            ldsm4(bfrD[1], &sW[buf][3][wn * 16 + (lm >> 1) * 8 + lr][kb + (lm & 1) * 8]);

            // B, C: hh only
            #pragma unroll
            for (int nt = 0; nt < 2; nt++)
                #pragma unroll
                for (int mt = 0; mt < 2; mt++) {
                    mma_f16(acc[0][mt][nt], afr[0][mt], &bfrB[nt * 2]);
                    mma_f16(acc[1][mt][nt], afr[0][mt], &bfrC[nt * 2]);
                }
            // dt: hh, hl, lh
            #pragma unroll
            for (int nt = 0; nt < 2; nt++)
                #pragma unroll
                for (int mt = 0; mt < 2; mt++) {
                    mma_f16(acc[2][mt][nt], afr[0][mt], &bfrD[0][nt * 2]);
                    mma_f16(acc[2][mt][nt], afr[0][mt], &bfrD[1][nt * 2]);
                    mma_f16(acc[2][mt][nt], afr[1][mt], &bfrD[0][nt * 2]);
                }
        }
        __syncthreads();
    }

    // ---- bias + negA hoist into smem (tiles dead; region beyond stage) ----
    float (*stage)[128][66] = (float (*)[128][66])smem_u16;   // [abar|bbar|cf][row][col]
    float* sbias = (float*)smem_u16 + 3 * 128 * 66;           // [4][64]
    if (tid < 256) {
        int a = tid >> 6, c = tid & 63;
        int nc = n0 + c;
        float v;
        if      (a == 0) v = bB[nc];
        else if (a == 1) v = bC[nc];
        else if (a == 2) v = bdt[nc];
        else             v = -__expf(Alog[nc]);
        sbias[a * 64 + c] = v;
    }
    __syncthreads();

    // ---- epilogue: transforms -> smem stage ----
    #pragma unroll
    for (int mt = 0; mt < 2; mt++) {
        #pragma unroll
        for (int nt = 0; nt < 2; nt++) {
            int lrow0 = wm * 32 + mt * 16 + g;
            int lcol0 = wn * 16 + nt * 8 + tg * 2;
            #pragma unroll
            for (int half = 0; half < 2; half++) {
                int lrow = lrow0 + half * 8;
                #pragma unroll
                for (int col = 0; col < 2; col++) {
                    int rg = half * 2 + col;
                    int lc = lcol0 + col;
                    float vB = acc[0][mt][nt][rg] + sbias[lc];
                    float vC = acc[1][mt][nt][rg] + sbias[64 + lc];
                    float t  = acc[2][mt][nt][rg] + sbias[128 + lc];
                    float dtv = (t > 20.f) ? t : log1pf(__expf(t));
                    float A = sbias[192 + lc];
                    stage[0][lrow][lc] = __expf(dtv * A);
                    stage[1][lrow][lc] = dtv * vB;
                    stage[2][lrow][lc] = vC;
                }
            }
        }
    }
    __syncthreads();

    // coalesced global writes: abar fp32 (float4), bbar/cf fp16 (half4 = uint2)
    #pragma unroll
    for (int j = 0; j < 4; j++) {               // abar: 2048 float4
        int i = tid + j * 512;
        int r = i >> 4, f = i & 15;
        float4 v;
        v.x = stage[0][r][f * 4 + 0];
        v.y = stage[0][r][f * 4 + 1];
        v.z = stage[0][r][f * 4 + 2];
        v.w = stage[0][r][f * 4 + 3];
        *(float4*)&g_abar[(m0 + r) * NN + n0 + f * 4] = v;
    }
    #pragma unroll
    for (int j = 0; j < 8; j++) {               // bbar/cf: 2 x 2048 half4
        int i = tid + j * 512;
        int a = i >> 11, rem = i & 2047, r = rem >> 4, f = rem & 15;
        union { __half2 b2[2]; uint2 u; } uu;
        uu.b2[0] = __floats2half2_rn(stage[1 + a][r][f * 4 + 0], stage[1 + a][r][f * 4 + 1]);
        uu.b2[1] = __floats2half2_rn(stage[1 + a][r][f * 4 + 2], stage[1 + a][r][f * 4 + 3]);
        __half* dst = a == 0 ? g_bbar2 : g_cf2;
        *(uint2*)&dst[(m0 + r) * NN + n0 + f * 4] = uu.u;
    }

    // fused scan pass 1: 16 chunks x 64 cols, 2 slots/thread
    #pragma unroll
    for (int t2 = 0; t2 < 2; t2++) {
        int slot = tid + t2 * 512;
        int ch  = slot >> 6;          // local chunk 0..15
        int col = slot & 63;
        float h = 0.f, p = 1.f;
        #pragma unroll
        for (int s = 0; s < LCH; s++) {
            float a  = stage[0][ch * LCH + s][col];
            float bb = stage[1][ch * LCH + s][col];
            h = fmaf(a, h, bb);
            p *= a;
        }
        int bidx = m0 >> 11;                       // batch
        int chg  = ((m0 & (SS - 1)) >> 3) + ch;    // global chunk in batch
        int o = (bidx * NCH + chg) * NN + n0 + col;
        g_Aprod[o] = p;
        g_Hend[o]  = h;
    }
}

// ---------------- 3) chunk combine: 8 chunks/lane + warp Kogge-Stone --------------
// One warp per (b, n); lane handles chunks (8L .. 8L+7).
__global__ void scan_combine() {
    int t    = blockIdx.x * blockDim.x + threadIdx.x;   // 131072 threads = 4096 warps
    int lane = t & 31;
    int w    = t >> 5;
    int n    = w & (NN - 1);
    int b    = w >> 11;
    int base = (b * NCH + 8 * lane) * NN + n;

    float a[8], h[8], APs[8], HPs[8];
    #pragma unroll
    for (int i = 0; i < 8; i++) {
        a[i] = g_Aprod[base + i * NN];
        h[i] = g_Hend [base + i * NN];
    }
    float Apre = 1.f, Hpre = 0.f;
    #pragma unroll
    for (int i = 0; i < 8; i++) {
        APs[i] = Apre; HPs[i] = Hpre;
        Hpre = fmaf(a[i], Hpre, h[i]);
        Apre *= a[i];
    }
    float A = Apre, H = Hpre;
    #pragma unroll
    for (int d = 1; d < 32; d <<= 1) {
        float al = __shfl_up_sync(0xFFFFFFFFu, A, d);
        float hl = __shfl_up_sync(0xFFFFFFFFu, H, d);
        if (lane >= d) {
            H = fmaf(A, hl, H);
            A *= al;
        }
    }
    float hex = __shfl_up_sync(0xFFFFFFFFu, H, 1);      // exclusive over groups
    float hs = (lane == 0) ? 0.f : hex;
    #pragma unroll
    for (int i = 0; i < 8; i++)
        g_Hstart[base + i * NN] = fmaf(APs[i], hs, HPs[i]);
}

// ---------------- 4) scan pass 2: replay with correct h0, emit y (fp16), 4-wide ---
__global__ void scan_pass2() {
    int t  = blockIdx.x * blockDim.x + threadIdx.x;     // 262144 threads
    int n4 = (t & 511) << 2;
    int ch = (t >> 9) & (NCH - 1);
    int b  = t >> 17;
    int base = (b * SS + ch * LCH) * NN + n4;
    const float4* pa = (const float4*)(g_abar + base);
    const uint2*  pb = (const uint2*)(g_bbar2 + base);
    const uint2*  pc = (const uint2*)(g_cf2 + base);
    uint2* y = (uint2*)(g_y + base);
    float4 h = *(const float4*)&g_Hstart[(b * NCH + ch) * NN + n4];
    #pragma unroll
    for (int s = 0; s < LCH; s++) {
        float4 a = pa[s * (NN / 4)];
        union { uint2 u; __half2 b2[2]; } ub, uc, uy;
        ub.u = pb[s * (NN / 4)];
        uc.u = pc[s * (NN / 4)];
        float2 b0 = __half22float2(ub.b2[0]), b1 = __half22float2(ub.b2[1]);
        float2 c0 = __half22float2(uc.b2[0]), c1 = __half22float2(uc.b2[1]);
        h.x = fmaf(a.x, h.x, b0.x);
        h.y = fmaf(a.y, h.y, b0.y);
        h.z = fmaf(a.z, h.z, b1.x);
        h.w = fmaf(a.w, h.w, b1.y);
        uy.b2[0] = __floats2half2_rn(c0.x * h.x, c0.y * h.y);
        uy.b2[1] = __floats2half2_rn(c1.x * h.z, c1.y * h.w);
        y[s * (NN / 4)] = uy.u;
    }
}

// ---------------- 5) output projection GEMM (split-K=4, cp.async pipelined) -------
// out[m,d] = sum_n y[m,n] * W_out[d,n].  y single fp16; W 2-split (2 passes).
// Block: 64 (m) x 128 (d), 512 K per block; 2 CTAs/SM -> single wave.
#define G2_SY_ELEMS (2*64*40)
#define G2_SW_ELEMS (2*2*128*40)
#define G2_SMEM ((G2_SY_ELEMS + G2_SW_ELEMS) * 2)

__global__ __launch_bounds__(256, 2)
void gemm2_out() {
    extern __shared__ unsigned short smem2_u16[];
    typedef unsigned short (*SYt)[64][40];
    typedef unsigned short (*SWot)[2][128][40];
    SYt  sY  = (SYt)smem2_u16;
    SWot sWo = (SWot)(smem2_u16 + G2_SY_ELEMS);

    const int tid  = threadIdx.x;
    const int warp = tid >> 5, lane = tid & 31;
    const int wm = warp >> 2, wn = warp & 3;
    const int m0 = blockIdx.x * 64;
    const int kp = blockIdx.y;              // 0..3
    const int g  = lane >> 2, tg = lane & 3;
    const int lm = lane >> 3, lr = lane & 7;

    float acc[2][4][4];
    #pragma unroll
    for (int a = 0; a < 2; a++)
        #pragma unroll
        for (int b = 0; b < 4; b++)
            #pragma unroll
            for (int c = 0; c < 4; c++) acc[a][b][c] = 0.f;

    auto load_tiles = [&](int buf, int kc) {
        const int kbase = kp * 512 + kc * 32;
        {                                           // y: 256 x 16B
            int i = tid;
            int r = i >> 2, w = i & 3;
            const __half* src = g_y + (m0 + r) * NN + kbase + w * 8;
            cp16(&sY[buf][r][w * 8], src);
        }
        #pragma unroll
        for (int j = 0; j < 4; j++) {               // W_out: 1024 x 16B
            int i = tid + j * 256;
            int sel = i >> 9, r = (i >> 2) & 127, w = i & 3;
            const __half* src = (sel ? g_Wol : g_Woh) + r * NN + kbase + w * 8;
            cp16(&sWo[buf][sel][r][w * 8], src);
        }
    };

    load_tiles(0, 0);
    CP_COMMIT();

    for (int kc = 0; kc < 16; kc++) {
        if (kc < 15) load_tiles((kc + 1) & 1, kc + 1);
        CP_COMMIT();
        CP_WAIT1();
        __syncthreads();
        const int buf = kc & 1;

        #pragma unroll
        for (int ks = 0; ks < 2; ks++) {
            const int kb = ks * 16;
            // hoisted A fragments (2 LDSM)
            unsigned afr[2][4];
            #pragma unroll
            for (int mt = 0; mt < 2; mt++)
                ldsm4(afr[mt],
                      &sY[buf][wm * 32 + mt * 16 + (lm & 1) * 8 + lr][kb + (lm >> 1) * 8]);
            // hoisted B fragments (4 LDSM)
            unsigned bfr[2][2][4];
            #pragma unroll
            for (int bs = 0; bs < 2; bs++)
                #pragma unroll
                for (int jp = 0; jp < 2; jp++)
                    ldsm4(bfr[bs][jp],
                          &sWo[buf][bs][wn * 32 + (jp * 2 + (lm >> 1)) * 8 + lr][kb + (lm & 1) * 8]);

            #pragma unroll
            for (int bs = 0; bs < 2; bs++) {        // yh*Wh + yh*Wl
                #pragma unroll
                for (int nt = 0; nt < 4; nt++) {
                    const unsigned* bp = &bfr[bs][nt >> 1][(nt & 1) * 2];
                    #pragma unroll
                    for (int mt = 0; mt < 2; mt++)
                        mma_f16(acc[mt][nt], afr[mt], bp);
                }
            }
        }
        __syncthreads();
    }

    // write deterministic split-K partials (float2 stores)
    float* part = g_part + kp * (MM * DD);
    #pragma unroll
    for (int mt = 0; mt < 2; mt++) {
        #pragma unroll
        for (int nt = 0; nt < 4; nt++) {
            int mr0 = m0 + wm * 32 + mt * 16 + g;
            int dc0 = wn * 32 + nt * 8 + tg * 2;
            #pragma unroll
            for (int half = 0; half < 2; half++) {
                int mr = mr0 + half * 8;
                float2 v;
                v.x = acc[mt][nt][half * 2 + 0];
                v.y = acc[mt][nt][half * 2 + 1];
                *(float2*)&part[mr * DD + dc0] = v;
            }
        }
    }
}

// ---------------- 6) reduce split-K partials + bias (float4) ----------------
__global__ void reduce_out(const float* __restrict__ bout, float* __restrict__ out) {
    int i = blockIdx.x * blockDim.x + threadIdx.x;    // 131072 threads
    if (i < MM * DD / 4) {
        const int MD = MM * DD;
        float4 v = *(const float4*)&bout[(i * 4) & (DD - 1)];
        float4 p0 = *(const float4*)&g_part[i * 4];
        float4 p1 = *(const float4*)&g_part[MD + i * 4];
        float4 p2 = *(const float4*)&g_part[2 * MD + i * 4];
        float4 p3 = *(const float4*)&g_part[3 * MD + i * 4];
        v.x += p0.x + p1.x + p2.x + p3.x;
        v.y += p0.y + p1.y + p2.y + p3.y;
        v.z += p0.z + p1.z + p2.z + p3.z;
        v.w += p0.w + p1.w + p2.w + p3.w;
        *(float4*)&out[i * 4] = v;
    }
}

// ---------------- launch ----------------
extern "C" void kernel_launch(void* const* d_in, const int* in_sizes, int n_in,
                              void* d_out, int out_size) {
    const float* x     = (const float*)d_in[0];
    const float* W_B   = (const float*)d_in[1];
    const float* b_B   = (const float*)d_in[2];
    const float* W_C   = (const float*)d_in[3];
    const float* b_C   = (const float*)d_in[4];
    const float* W_dt  = (const float*)d_in[5];
    const float* b_dt  = (const float*)d_in[6];
    const float* A_log = (const float*)d_in[7];
    const float* W_out = (const float*)d_in[8];
    const float* b_out = (const float*)d_in[9];
    float* out = (float*)d_out;

    cudaFuncSetAttribute(gemm1_proj, cudaFuncAttributeMaxDynamicSharedMemorySize, G1_SMEM);
    cudaFuncSetAttribute(gemm2_out,  cudaFuncAttributeMaxDynamicSharedMemorySize, G2_SMEM);

    split_kernel<<<1536, 256>>>(x, W_B, W_C, W_dt, W_out);
    gemm1_proj<<<dim3(32, 32), 512, G1_SMEM>>>(b_B, b_C, b_dt, A_log);
    scan_combine<<<512, 256>>>();
    scan_pass2<<<1024, 256>>>();
    gemm2_out<<<dim3(64, 4), 256, G2_SMEM>>>();
    reduce_out<<<512, 256>>>(b_out, out);
}

// round 14
// speedup vs baseline: 1.0514x; 1.0514x over previous
#include <cuda_runtime.h>
#include <cuda_fp16.h>
#include <math.h>

// Problem constants
#define BB   2
#define SS   2048
#define DD   128
#define NN   2048
#define MM   (BB * SS)          // 4096 rows
#define NCH  256                // scan chunks
#define LCH  8                  // steps per chunk (NCH*LCH == SS)

// ---------------- scratch (static device globals; no allocations) ----------------
__device__ __half g_xh[MM * DD], g_xl[MM * DD];                  // fp16 split x
__device__ __half g_Wh[3 * NN * DD], g_Wl[3 * NN * DD];          // fp16 split [W_B; W_C; W_dt]
__device__ __half g_Woh[DD * NN], g_Wol[DD * NN];                // fp16 split W_out
__device__ float  g_abar[MM * NN];                               // exp(dt*A)   (fp32: scan-critical)
__device__ __half g_bbar2[MM * NN];                              // dt*B_feat   (fp16)
__device__ __half g_cf2  [MM * NN];                              // C_feat      (fp16)
__device__ __half g_y[MM * NN];                                  // y = c*h     (single fp16)
__device__ float g_Aprod [BB * NCH * NN];
__device__ float g_Hend  [BB * NCH * NN];
__device__ float g_Hstart[BB * NCH * NN];
__device__ float g_part[4 * MM * DD];                            // split-K partials

// ---------------- helpers ----------------
__device__ __forceinline__ void f16_split(float v, __half& h, __half& l) {
    h = __float2half_rn(v);
    l = __float2half_rn(v - __half2float(h));
}

__device__ __forceinline__ void mma_f16(float* c, const unsigned* a, const unsigned* b) {
    asm volatile(
        "mma.sync.aligned.m16n8k16.row.col.f32.f16.f16.f32 "
        "{%0,%1,%2,%3}, {%4,%5,%6,%7}, {%8,%9}, {%0,%1,%2,%3};\n"
        : "+f"(c[0]), "+f"(c[1]), "+f"(c[2]), "+f"(c[3])
        : "r"(a[0]), "r"(a[1]), "r"(a[2]), "r"(a[3]),
          "r"(b[0]), "r"(b[1]));
}

__device__ __forceinline__ void ldsm4(unsigned* r, const void* p) {
    unsigned a = (unsigned)__cvta_generic_to_shared(p);
    asm volatile("ldmatrix.sync.aligned.m8n8.x4.shared.b16 {%0,%1,%2,%3}, [%4];"
                 : "=r"(r[0]), "=r"(r[1]), "=r"(r[2]), "=r"(r[3]) : "r"(a));
}

__device__ __forceinline__ void cp16(void* smem_dst, const void* gmem_src) {
    unsigned s = (unsigned)__cvta_generic_to_shared(smem_dst);
    asm volatile("cp.async.cg.shared.global [%0], [%1], 16;\n" :: "r"(s), "l"(gmem_src));
}
#define CP_COMMIT() asm volatile("cp.async.commit_group;\n" ::: "memory")
#define CP_WAIT1()  asm volatile("cp.async.wait_group 1;\n" ::: "memory")

// ---------------- 0) split inputs into fp16 hi/lo (x4 vectorized) ----------------
__global__ void split_kernel(const float* __restrict__ x,
                             const float* __restrict__ WB,
                             const float* __restrict__ WC,
                             const float* __restrict__ Wdt,
                             const float* __restrict__ Wout) {
    const int XE  = MM * DD;        // 524288
    const int WE  = NN * DD;        // 262144 per matrix
    const int WOE = DD * NN;        // 262144
    int i4 = (blockIdx.x * blockDim.x + threadIdx.x) * 4;

    const float* src;
    __half *dh, *dl;
    int off;
    if (i4 < XE) {
        src = x; off = i4; dh = g_xh; dl = g_xl;
    } else if (i4 < XE + 3 * WE) {
        int j = i4 - XE;
        src = (j < WE) ? WB : ((j < 2 * WE) ? WC : Wdt);
        off = j % WE; dh = g_Wh + (j - off); dl = g_Wl + (j - off);
    } else if (i4 < XE + 3 * WE + WOE) {
        int j = i4 - XE - 3 * WE;
        src = Wout; off = j; dh = g_Woh; dl = g_Wol;
    } else return;

    float4 v = *(const float4*)&src[off];
    __half h0, l0, h1, l1, h2, l2, h3, l3;
    f16_split(v.x, h0, l0); f16_split(v.y, h1, l1);
    f16_split(v.z, h2, l2); f16_split(v.w, h3, l3);
    union { __half2 b2[2]; uint2 u; } uh, ul;
    uh.b2[0] = __halves2half2(h0, h1); uh.b2[1] = __halves2half2(h2, h3);
    ul.b2[0] = __halves2half2(l0, l1); ul.b2[1] = __halves2half2(l2, l3);
    *(uint2*)&dh[off] = uh.u;
    *(uint2*)&dl[off] = ul.u;
}

// ---------------- 1) fused projection GEMM + featurizer + chunk-scan pass 1 -------
// Block tile: 128 (m) x 32 (n) per matrix, K=128 in 4 chunks of 32, cp.async 2-buf.
// 2 CTAs/SM (proven critical: co-resident CTA hides serial epilogue phases).
// fp16 2-split. Passes: hh only for W_B/W_C; (hh, hl, lh) for W_dt (scan-critical).
// An m-block = 16 scan chunks (LCH=8); scan pass-1 in-CTA, 2 slots/thread.
#define G1_SX_ELEMS (2*2*128*40)         // [buf][sel][row][pitch40] shorts
#define G1_SW_ELEMS (2*3*2*32*40)        // [buf][mat][sel][row][pitch40] shorts
#define G1_SMEM ((G1_SX_ELEMS + G1_SW_ELEMS) * 2)   // 71,680 B (stage reuses this)

__global__ __launch_bounds__(256, 2)
void gemm1_proj(const float* __restrict__ bB, const float* __restrict__ bC,
                const float* __restrict__ bdt, const float* __restrict__ Alog) {
    extern __shared__ unsigned short smem_u16[];
    typedef unsigned short (*SXt)[2][128][40];
    typedef unsigned short (*SWt)[3][2][32][40];
    SXt sX = (SXt)smem_u16;
    SWt sW = (SWt)(smem_u16 + G1_SX_ELEMS);

    const int tid  = threadIdx.x;
    const int warp = tid >> 5, lane = tid & 31;
    const int wm = warp >> 1, wn = warp & 1;
    const int m0 = blockIdx.y * 128;
    const int n0 = blockIdx.x * 32;
    const int g  = lane >> 2, tg = lane & 3;
    const int lm = lane >> 3, lr = lane & 7;     // ldmatrix lane decomposition

    float acc[3][2][2][4];
    #pragma unroll
    for (int a = 0; a < 3; a++)
        #pragma unroll
        for (int b = 0; b < 2; b++)
            #pragma unroll
            for (int c = 0; c < 2; c++)
                #pragma unroll
                for (int d = 0; d < 4; d++) acc[a][b][c][d] = 0.f;

    // async tile loader for k-chunk kc into buffer buf
    // W combos loaded: (B,h) (C,h) (dt,h) (dt,l)
    auto load_tiles = [&](int buf, int kc) {
        #pragma unroll
        for (int j = 0; j < 4; j++) {               // x: 1024 x 16B
            int i = tid + j * 256;
            int sel = i >> 9, r = (i >> 2) & 127, w = i & 3;
            const __half* src = (sel ? g_xl : g_xh) + (m0 + r) * DD + kc * 32 + w * 8;
            cp16(&sX[buf][sel][r][w * 8], src);
        }
        #pragma unroll
        for (int j = 0; j < 2; j++) {               // W: 512 x 16B
            int i = tid + j * 256;
            int combo = i >> 7, r = (i >> 2) & 31, w = i & 3;
            int mat = (combo < 3) ? combo : 2;
            int sel = (combo == 3) ? 1 : 0;
            const __half* src = (sel ? g_Wl : g_Wh) + (mat * NN + n0 + r) * DD + kc * 32 + w * 8;
            cp16(&sW[buf][mat][sel][r][w * 8], src);
        }
    };

    load_tiles(0, 0);
    CP_COMMIT();

    for (int kc = 0; kc < 4; kc++) {
        if (kc < 3) load_tiles((kc + 1) & 1, kc + 1);
        CP_COMMIT();                 // real group, or empty group on last iter
        CP_WAIT1();                  // forces chunk-kc group completion
        __syncthreads();
        const int buf = kc & 1;

        #pragma unroll
        for (int ks = 0; ks < 2; ks++) {
            const int kb = ks * 16;
            // hoisted A fragments: [sel][mt][4 regs]  (4 LDSM)
            unsigned afr[2][2][4];
            #pragma unroll
            for (int as = 0; as < 2; as++)
                #pragma unroll
                for (int mt = 0; mt < 2; mt++)
                    ldsm4(afr[as][mt],
                          &sX[buf][as][wm * 32 + mt * 16 + (lm & 1) * 8 + lr][kb + (lm >> 1) * 8]);
            // hoisted B fragments (4 LDSM): B.h, C.h, dt.h, dt.l
            unsigned bfrB[4], bfrC[4], bfrD[2][4];
            ldsm4(bfrB,    &sW[buf][0][0][wn * 16 + (lm >> 1) * 8 + lr][kb + (lm & 1) * 8]);
            ldsm4(bfrC,    &sW[buf][1][0][wn * 16 + (lm >> 1) * 8 + lr][kb + (lm & 1) * 8]);
            ldsm4(bfrD[0], &sW[buf][2][0][wn * 16 + (lm >> 1) * 8 + lr][kb + (lm & 1) * 8]);
            ldsm4(bfrD[1], &sW[buf][2][1][wn * 16 + (lm >> 1) * 8 + lr][kb + (lm & 1) * 8]);

            // B, C: hh only
            #pragma unroll
            for (int nt = 0; nt < 2; nt++)
                #pragma unroll
                for (int mt = 0; mt < 2; mt++) {
                    mma_f16(acc[0][mt][nt], afr[0][mt], &bfrB[nt * 2]);
                    mma_f16(acc[1][mt][nt], afr[0][mt], &bfrC[nt * 2]);
                }
            // dt: hh, hl, lh
            #pragma unroll
            for (int nt = 0; nt < 2; nt++)
                #pragma unroll
                for (int mt = 0; mt < 2; mt++) {
                    mma_f16(acc[2][mt][nt], afr[0][mt], &bfrD[0][nt * 2]);
                    mma_f16(acc[2][mt][nt], afr[0][mt], &bfrD[1][nt * 2]);
                    mma_f16(acc[2][mt][nt], afr[1][mt], &bfrD[0][nt * 2]);
                }
        }
        __syncthreads();
    }

    // ---- bias + negA hoist into smem (tiles dead; region beyond stage) ----
    float (*stage)[128][34] = (float (*)[128][34])smem_u16;   // [abar|bbar|cf][row][col]
    float* sbias = (float*)smem_u16 + 3 * 128 * 34;           // [4][32]
    if (tid < 128) {
        int a = tid >> 5, c = tid & 31;
        int nc = n0 + c;
        float v;
        if      (a == 0) v = bB[nc];
        else if (a == 1) v = bC[nc];
        else if (a == 2) v = bdt[nc];
        else             v = -__expf(Alog[nc]);
        sbias[a * 32 + c] = v;
    }
    __syncthreads();

    // ---- epilogue: transforms -> smem stage ----
    #pragma unroll
    for (int mt = 0; mt < 2; mt++) {
        #pragma unroll
        for (int nt = 0; nt < 2; nt++) {
            int lrow0 = wm * 32 + mt * 16 + g;
            int lcol0 = wn * 16 + nt * 8 + tg * 2;
            #pragma unroll
            for (int half = 0; half < 2; half++) {
                int lrow = lrow0 + half * 8;
                #pragma unroll
                for (int col = 0; col < 2; col++) {
                    int rg = half * 2 + col;
                    int lc = lcol0 + col;
                    float vB = acc[0][mt][nt][rg] + sbias[lc];
                    float vC = acc[1][mt][nt][rg] + sbias[32 + lc];
                    float t  = acc[2][mt][nt][rg] + sbias[64 + lc];
                    float dtv = (t > 20.f) ? t : log1pf(__expf(t));
                    float A = sbias[96 + lc];
                    stage[0][lrow][lc] = __expf(dtv * A);
                    stage[1][lrow][lc] = dtv * vB;
                    stage[2][lrow][lc] = vC;
                }
            }
        }
    }
    __syncthreads();

    // coalesced global writes: abar fp32 (float4), bbar/cf fp16 (half4 = uint2)
    #pragma unroll
    for (int j = 0; j < 4; j++) {               // abar: 1024 float4
        int i = tid + j * 256;
        int r = i >> 3, f = i & 7;
        float4 v;
        v.x = stage[0][r][f * 4 + 0];
        v.y = stage[0][r][f * 4 + 1];
        v.z = stage[0][r][f * 4 + 2];
        v.w = stage[0][r][f * 4 + 3];
        *(float4*)&g_abar[(m0 + r) * NN + n0 + f * 4] = v;
    }
    #pragma unroll
    for (int j = 0; j < 8; j++) {               // bbar/cf: 2 x 1024 half4
        int i = tid + j * 256;
        int a = i >> 10, rem = i & 1023, r = rem >> 3, f = rem & 7;
        union { __half2 b2[2]; uint2 u; } uu;
        uu.b2[0] = __floats2half2_rn(stage[1 + a][r][f * 4 + 0], stage[1 + a][r][f * 4 + 1]);
        uu.b2[1] = __floats2half2_rn(stage[1 + a][r][f * 4 + 2], stage[1 + a][r][f * 4 + 3]);
        __half* dst = a == 0 ? g_bbar2 : g_cf2;
        *(uint2*)&dst[(m0 + r) * NN + n0 + f * 4] = uu.u;
    }

    // fused scan pass 1: 16 chunks x 32 cols, 2 slots/thread
    #pragma unroll
    for (int t2 = 0; t2 < 2; t2++) {
        int slot = tid + t2 * 256;
        int ch  = slot >> 5;          // local chunk 0..15
        int col = slot & 31;
        float h = 0.f, p = 1.f;
        #pragma unroll
        for (int s = 0; s < LCH; s++) {
            float a  = stage[0][ch * LCH + s][col];
            float bb = stage[1][ch * LCH + s][col];
            h = fmaf(a, h, bb);
            p *= a;
        }
        int bidx = m0 >> 11;                       // batch
        int chg  = ((m0 & (SS - 1)) >> 3) + ch;    // global chunk in batch
        int o = (bidx * NCH + chg) * NN + n0 + col;
        g_Aprod[o] = p;
        g_Hend[o]  = h;
    }
}

// ---------------- 3) chunk combine: 8 chunks/lane + warp Kogge-Stone --------------
// One warp per (b, n); lane handles chunks (8L .. 8L+7).
__global__ void scan_combine() {
    int t    = blockIdx.x * blockDim.x + threadIdx.x;   // 131072 threads = 4096 warps
    int lane = t & 31;
    int w    = t >> 5;
    int n    = w & (NN - 1);
    int b    = w >> 11;
    int base = (b * NCH + 8 * lane) * NN + n;

    float a[8], h[8], APs[8], HPs[8];
    #pragma unroll
    for (int i = 0; i < 8; i++) {
        a[i] = g_Aprod[base + i * NN];
        h[i] = g_Hend [base + i * NN];
    }
    float Apre = 1.f, Hpre = 0.f;
    #pragma unroll
    for (int i = 0; i < 8; i++) {
        APs[i] = Apre; HPs[i] = Hpre;
        Hpre = fmaf(a[i], Hpre, h[i]);
        Apre *= a[i];
    }
    float A = Apre, H = Hpre;
    #pragma unroll
    for (int d = 1; d < 32; d <<= 1) {
        float al = __shfl_up_sync(0xFFFFFFFFu, A, d);
        float hl = __shfl_up_sync(0xFFFFFFFFu, H, d);
        if (lane >= d) {
            H = fmaf(A, hl, H);
            A *= al;
        }
    }
    float hex = __shfl_up_sync(0xFFFFFFFFu, H, 1);      // exclusive over groups
    float hs = (lane == 0) ? 0.f : hex;
    #pragma unroll
    for (int i = 0; i < 8; i++)
        g_Hstart[base + i * NN] = fmaf(APs[i], hs, HPs[i]);
}

// ---------------- 4) scan pass 2: replay with correct h0, emit y (fp16), 4-wide ---
__global__ void scan_pass2() {
    int t  = blockIdx.x * blockDim.x + threadIdx.x;     // 262144 threads
    int n4 = (t & 511) << 2;
    int ch = (t >> 9) & (NCH - 1);
    int b  = t >> 17;
    int base = (b * SS + ch * LCH) * NN + n4;
    const float4* pa = (const float4*)(g_abar + base);
    const uint2*  pb = (const uint2*)(g_bbar2 + base);
    const uint2*  pc = (const uint2*)(g_cf2 + base);
    uint2* y = (uint2*)(g_y + base);
    float4 h = *(const float4*)&g_Hstart[(b * NCH + ch) * NN + n4];
    #pragma unroll
    for (int s = 0; s < LCH; s++) {
        float4 a = pa[s * (NN / 4)];
        union { uint2 u; __half2 b2[2]; } ub, uc, uy;
        ub.u = pb[s * (NN / 4)];
        uc.u = pc[s * (NN / 4)];
        float2 b0 = __half22float2(ub.b2[0]), b1 = __half22float2(ub.b2[1]);
        float2 c0 = __half22float2(uc.b2[0]), c1 = __half22float2(uc.b2[1]);
        h.x = fmaf(a.x, h.x, b0.x);
        h.y = fmaf(a.y, h.y, b0.y);
        h.z = fmaf(a.z, h.z, b1.x);
        h.w = fmaf(a.w, h.w, b1.y);
        uy.b2[0] = __floats2half2_rn(c0.x * h.x, c0.y * h.y);
        uy.b2[1] = __floats2half2_rn(c1.x * h.z, c1.y * h.w);
        y[s * (NN / 4)] = uy.u;
    }
}

// ---------------- 5) output projection GEMM (split-K=4, cp.async pipelined) -------
// out[m,d] = sum_n y[m,n] * W_out[d,n].  y single fp16; W 2-split (2 passes).
// Block: 64 (m) x 128 (d), 512 K per block; 2 CTAs/SM -> single wave.
#define G2_SY_ELEMS (2*64*40)
#define G2_SW_ELEMS (2*2*128*40)
#define G2_SMEM ((G2_SY_ELEMS + G2_SW_ELEMS) * 2)

__global__ __launch_bounds__(256, 2)
void gemm2_out() {
    extern __shared__ unsigned short smem2_u16[];
    typedef unsigned short (*SYt)[64][40];
    typedef unsigned short (*SWot)[2][128][40];
    SYt  sY  = (SYt)smem2_u16;
    SWot sWo = (SWot)(smem2_u16 + G2_SY_ELEMS);

    const int tid  = threadIdx.x;
    const int warp = tid >> 5, lane = tid & 31;
    const int wm = warp >> 2, wn = warp & 3;
    const int m0 = blockIdx.x * 64;
    const int kp = blockIdx.y;              // 0..3
    const int g  = lane >> 2, tg = lane & 3;
    const int lm = lane >> 3, lr = lane & 7;

    float acc[2][4][4];
    #pragma unroll
    for (int a = 0; a < 2; a++)
        #pragma unroll
        for (int b = 0; b < 4; b++)
            #pragma unroll
            for (int c = 0; c < 4; c++) acc[a][b][c] = 0.f;

    auto load_tiles = [&](int buf, int kc) {
        const int kbase = kp * 512 + kc * 32;
        {                                           // y: 256 x 16B
            int i = tid;
            int r = i >> 2, w = i & 3;
            const __half* src = g_y + (m0 + r) * NN + kbase + w * 8;
            cp16(&sY[buf][r][w * 8], src);
        }
        #pragma unroll
        for (int j = 0; j < 4; j++) {               // W_out: 1024 x 16B
            int i = tid + j * 256;
            int sel = i >> 9, r = (i >> 2) & 127, w = i & 3;
            const __half* src = (sel ? g_Wol : g_Woh) + r * NN + kbase + w * 8;
            cp16(&sWo[buf][sel][r][w * 8], src);
        }
    };

    load_tiles(0, 0);
    CP_COMMIT();

    for (int kc = 0; kc < 16; kc++) {
        if (kc < 15) load_tiles((kc + 1) & 1, kc + 1);
        CP_COMMIT();
        CP_WAIT1();
        __syncthreads();
        const int buf = kc & 1;

        #pragma unroll
        for (int ks = 0; ks < 2; ks++) {
            const int kb = ks * 16;
            // hoisted A fragments (2 LDSM)
            unsigned afr[2][4];
            #pragma unroll
            for (int mt = 0; mt < 2; mt++)
                ldsm4(afr[mt],
                      &sY[buf][wm * 32 + mt * 16 + (lm & 1) * 8 + lr][kb + (lm >> 1) * 8]);
            // hoisted B fragments (4 LDSM)
            unsigned bfr[2][2][4];
            #pragma unroll
            for (int bs = 0; bs < 2; bs++)
                #pragma unroll
                for (int jp = 0; jp < 2; jp++)
                    ldsm4(bfr[bs][jp],
                          &sWo[buf][bs][wn * 32 + (jp * 2 + (lm >> 1)) * 8 + lr][kb + (lm & 1) * 8]);

            #pragma unroll
            for (int bs = 0; bs < 2; bs++) {        // yh*Wh + yh*Wl
                #pragma unroll
                for (int nt = 0; nt < 4; nt++) {
                    const unsigned* bp = &bfr[bs][nt >> 1][(nt & 1) * 2];
                    #pragma unroll
                    for (int mt = 0; mt < 2; mt++)
                        mma_f16(acc[mt][nt], afr[mt], bp);
                }
            }
        }
        __syncthreads();
    }

    // write deterministic split-K partials (float2 stores)
    float* part = g_part + kp * (MM * DD);
    #pragma unroll
    for (int mt = 0; mt < 2; mt++) {
        #pragma unroll
        for (int nt = 0; nt < 4; nt++) {
            int mr0 = m0 + wm * 32 + mt * 16 + g;
            int dc0 = wn * 32 + nt * 8 + tg * 2;
            #pragma unroll
            for (int half = 0; half < 2; half++) {
                int mr = mr0 + half * 8;
                float2 v;
                v.x = acc[mt][nt][half * 2 + 0];
                v.y = acc[mt][nt][half * 2 + 1];
                *(float2*)&part[mr * DD + dc0] = v;
            }
        }
    }
}

// ---------------- 6) reduce split-K partials + bias (float4) ----------------
__global__ void reduce_out(const float* __restrict__ bout, float* __restrict__ out) {
    int i = blockIdx.x * blockDim.x + threadIdx.x;    // 131072 threads
    if (i < MM * DD / 4) {
        const int MD = MM * DD;
        float4 v = *(const float4*)&bout[(i * 4) & (DD - 1)];
        float4 p0 = *(const float4*)&g_part[i * 4];
        float4 p1 = *(const float4*)&g_part[MD + i * 4];
        float4 p2 = *(const float4*)&g_part[2 * MD + i * 4];
        float4 p3 = *(const float4*)&g_part[3 * MD + i * 4];
        v.x += p0.x + p1.x + p2.x + p3.x;
        v.y += p0.y + p1.y + p2.y + p3.y;
        v.z += p0.z + p1.z + p2.z + p3.z;
        v.w += p0.w + p1.w + p2.w + p3.w;
        *(float4*)&out[i * 4] = v;
    }
}

// ---------------- launch ----------------
extern "C" void kernel_launch(void* const* d_in, const int* in_sizes, int n_in,
                              void* d_out, int out_size) {
    const float* x     = (const float*)d_in[0];
    const float* W_B   = (const float*)d_in[1];
    const float* b_B   = (const float*)d_in[2];
    const float* W_C   = (const float*)d_in[3];
    const float* b_C   = (const float*)d_in[4];
    const float* W_dt  = (const float*)d_in[5];
    const float* b_dt  = (const float*)d_in[6];
    const float* A_log = (const float*)d_in[7];
    const float* W_out = (const float*)d_in[8];
    const float* b_out = (const float*)d_in[9];
    float* out = (float*)d_out;

    cudaFuncSetAttribute(gemm1_proj, cudaFuncAttributeMaxDynamicSharedMemorySize, G1_SMEM);
    cudaFuncSetAttribute(gemm2_out,  cudaFuncAttributeMaxDynamicSharedMemorySize, G2_SMEM);

    split_kernel<<<1536, 256>>>(x, W_B, W_C, W_dt, W_out);
    gemm1_proj<<<dim3(64, 32), 256, G1_SMEM>>>(b_B, b_C, b_dt, A_log);
    scan_combine<<<512, 256>>>();
    scan_pass2<<<1024, 256>>>();
    gemm2_out<<<dim3(64, 4), 256, G2_SMEM>>>();
    reduce_out<<<512, 256>>>(b_out, out);
}

// round 15
// speedup vs baseline: 1.1526x; 1.0963x over previous
#include <cuda_runtime.h>
#include <cuda_fp16.h>
#include <math.h>

// Problem constants
#define BB   2
#define SS   2048
#define DD   128
#define NN   2048
#define MM   (BB * SS)          // 4096 rows
#define NCH  128                // scan chunks
#define LCH  16                 // steps per chunk (NCH*LCH == SS)

// ---------------- scratch (static device globals; no allocations) ----------------
__device__ __half g_xh[MM * DD];                                 // fp16 x (hi only)
__device__ __half g_Wh[3 * NN * DD], g_Wl[3 * NN * DD];          // fp16 split [W_B; W_C; W_dt]
__device__ __half g_Woh[DD * NN], g_Wol[DD * NN];                // fp16 split W_out
__device__ float  g_abar[MM * NN];                               // exp(dt*A)   (fp32: scan-critical)
__device__ __half g_bbar2[MM * NN];                              // dt*B_feat   (fp16)
__device__ __half g_cf2  [MM * NN];                              // C_feat      (fp16)
__device__ __half g_y[MM * NN];                                  // y = c*h     (single fp16)
__device__ float g_Aprod [BB * NCH * NN];
__device__ float g_Hend  [BB * NCH * NN];
__device__ float g_Hstart[BB * NCH * NN];
__device__ float g_part[4 * MM * DD];                            // split-K partials
__device__ int   g_cnt[64];                                      // split-K completion counters

// ---------------- helpers ----------------
__device__ __forceinline__ void f16_split(float v, __half& h, __half& l) {
    h = __float2half_rn(v);
    l = __float2half_rn(v - __half2float(h));
}

__device__ __forceinline__ void mma_f16(float* c, const unsigned* a, const unsigned* b) {
    asm volatile(
        "mma.sync.aligned.m16n8k16.row.col.f32.f16.f16.f32 "
        "{%0,%1,%2,%3}, {%4,%5,%6,%7}, {%8,%9}, {%0,%1,%2,%3};\n"
        : "+f"(c[0]), "+f"(c[1]), "+f"(c[2]), "+f"(c[3])
        : "r"(a[0]), "r"(a[1]), "r"(a[2]), "r"(a[3]),
          "r"(b[0]), "r"(b[1]));
}

__device__ __forceinline__ void ldsm4(unsigned* r, const void* p) {
    unsigned a = (unsigned)__cvta_generic_to_shared(p);
    asm volatile("ldmatrix.sync.aligned.m8n8.x4.shared.b16 {%0,%1,%2,%3}, [%4];"
                 : "=r"(r[0]), "=r"(r[1]), "=r"(r[2]), "=r"(r[3]) : "r"(a));
}

__device__ __forceinline__ void cp16(void* smem_dst, const void* gmem_src) {
    unsigned s = (unsigned)__cvta_generic_to_shared(smem_dst);
    asm volatile("cp.async.cg.shared.global [%0], [%1], 16;\n" :: "r"(s), "l"(gmem_src));
}
#define CP_COMMIT() asm volatile("cp.async.commit_group;\n" ::: "memory")
#define CP_WAIT1()  asm volatile("cp.async.wait_group 1;\n" ::: "memory")

// ---------------- 0) split inputs: x -> fp16 hi; W -> fp16 hi/lo (x4 vectorized) --
__global__ void split_kernel(const float* __restrict__ x,
                             const float* __restrict__ WB,
                             const float* __restrict__ WC,
                             const float* __restrict__ Wdt,
                             const float* __restrict__ Wout) {
    const int XE  = MM * DD;        // 524288
    const int WE  = NN * DD;        // 262144 per matrix
    const int WOE = DD * NN;        // 262144
    int i4 = (blockIdx.x * blockDim.x + threadIdx.x) * 4;

    if (i4 < XE) {                  // x: hi only
        float4 v = *(const float4*)&x[i4];
        union { __half2 b2[2]; uint2 u; } uh;
        uh.b2[0] = __floats2half2_rn(v.x, v.y);
        uh.b2[1] = __floats2half2_rn(v.z, v.w);
        *(uint2*)&g_xh[i4] = uh.u;
        return;
    }
    const float* src;
    __half *dh, *dl;
    int off;
    if (i4 < XE + 3 * WE) {
        int j = i4 - XE;
        src = (j < WE) ? WB : ((j < 2 * WE) ? WC : Wdt);
        off = j % WE; dh = g_Wh + (j - off); dl = g_Wl + (j - off);
    } else if (i4 < XE + 3 * WE + WOE) {
        int j = i4 - XE - 3 * WE;
        src = Wout; off = j; dh = g_Woh; dl = g_Wol;
    } else return;

    float4 v = *(const float4*)&src[off];
    __half h0, l0, h1, l1, h2, l2, h3, l3;
    f16_split(v.x, h0, l0); f16_split(v.y, h1, l1);
    f16_split(v.z, h2, l2); f16_split(v.w, h3, l3);
    union { __half2 b2[2]; uint2 u; } uh, ul;
    uh.b2[0] = __halves2half2(h0, h1); uh.b2[1] = __halves2half2(h2, h3);
    ul.b2[0] = __halves2half2(l0, l1); ul.b2[1] = __halves2half2(l2, l3);
    *(uint2*)&dh[off] = uh.u;
    *(uint2*)&dl[off] = ul.u;
}

// ---------------- 1) fused projection GEMM + featurizer + chunk-scan pass 1 -------
// Block tile: 128 (m) x 32 (n) per matrix, K=128 in 4 chunks of 32, cp.async 2-buf.
// 2 CTAs/SM (co-resident CTA hides serial epilogue phases — proven critical).
// x single fp16 (hi). Passes: hh for W_B/W_C; (hh, hl) for W_dt.
// An m-block = 8 scan chunks (LCH=16); scan pass-1 in-CTA from the smem stage.
#define G1_SX_ELEMS (2*128*40)           // [buf][row][pitch40] shorts (x hi only)
#define G1_SW_ELEMS (2*3*2*32*40)        // [buf][mat][sel][row][pitch40] shorts
#define G1_TILES ((G1_SX_ELEMS + G1_SW_ELEMS) * 2)          // 51,200 B
#define G1_SMEM  52736                                      // stage (52,736 B) > tiles

__global__ __launch_bounds__(256, 2)
void gemm1_proj(const float* __restrict__ bB, const float* __restrict__ bC,
                const float* __restrict__ bdt, const float* __restrict__ Alog) {
    extern __shared__ unsigned short smem_u16[];
    typedef unsigned short (*SXt)[128][40];
    typedef unsigned short (*SWt)[3][2][32][40];
    SXt sX = (SXt)smem_u16;
    SWt sW = (SWt)(smem_u16 + G1_SX_ELEMS);

    const int tid  = threadIdx.x;
    const int warp = tid >> 5, lane = tid & 31;
    const int wm = warp >> 1, wn = warp & 1;
    const int m0 = blockIdx.y * 128;
    const int n0 = blockIdx.x * 32;
    const int g  = lane >> 2, tg = lane & 3;
    const int lm = lane >> 3, lr = lane & 7;     // ldmatrix lane decomposition

    float acc[3][2][2][4];
    #pragma unroll
    for (int a = 0; a < 3; a++)
        #pragma unroll
        for (int b = 0; b < 2; b++)
            #pragma unroll
            for (int c = 0; c < 2; c++)
                #pragma unroll
                for (int d = 0; d < 4; d++) acc[a][b][c][d] = 0.f;

    // async tile loader for k-chunk kc into buffer buf
    // W combos loaded: (B,h) (C,h) (dt,h) (dt,l)
    auto load_tiles = [&](int buf, int kc) {
        #pragma unroll
        for (int j = 0; j < 2; j++) {               // x: 512 x 16B
            int i = tid + j * 256;
            int r = (i >> 2) & 127, w = i & 3;
            const __half* src = g_xh + (m0 + r) * DD + kc * 32 + w * 8;
            cp16(&sX[buf][r][w * 8], src);
        }
        #pragma unroll
        for (int j = 0; j < 2; j++) {               // W: 512 x 16B
            int i = tid + j * 256;
            int combo = i >> 7, r = (i >> 2) & 31, w = i & 3;
            int mat = (combo < 3) ? combo : 2;
            int sel = (combo == 3) ? 1 : 0;
            const __half* src = (sel ? g_Wl : g_Wh) + (mat * NN + n0 + r) * DD + kc * 32 + w * 8;
            cp16(&sW[buf][mat][sel][r][w * 8], src);
        }
    };

    load_tiles(0, 0);
    CP_COMMIT();

    for (int kc = 0; kc < 4; kc++) {
        if (kc < 3) load_tiles((kc + 1) & 1, kc + 1);
        CP_COMMIT();                 // real group, or empty group on last iter
        CP_WAIT1();                  // forces chunk-kc group completion
        __syncthreads();
        const int buf = kc & 1;

        #pragma unroll
        for (int ks = 0; ks < 2; ks++) {
            const int kb = ks * 16;
            // hoisted A fragments (2 LDSM)
            unsigned afr[2][4];
            #pragma unroll
            for (int mt = 0; mt < 2; mt++)
                ldsm4(afr[mt],
                      &sX[buf][wm * 32 + mt * 16 + (lm & 1) * 8 + lr][kb + (lm >> 1) * 8]);
            // hoisted B fragments (4 LDSM): B.h, C.h, dt.h, dt.l
            unsigned bfrB[4], bfrC[4], bfrD[2][4];
            ldsm4(bfrB,    &sW[buf][0][0][wn * 16 + (lm >> 1) * 8 + lr][kb + (lm & 1) * 8]);
            ldsm4(bfrC,    &sW[buf][1][0][wn * 16 + (lm >> 1) * 8 + lr][kb + (lm & 1) * 8]);
            ldsm4(bfrD[0], &sW[buf][2][0][wn * 16 + (lm >> 1) * 8 + lr][kb + (lm & 1) * 8]);
            ldsm4(bfrD[1], &sW[buf][2][1][wn * 16 + (lm >> 1) * 8 + lr][kb + (lm & 1) * 8]);

            // B, C: hh; dt: hh + hl
            #pragma unroll
            for (int nt = 0; nt < 2; nt++)
                #pragma unroll
                for (int mt = 0; mt < 2; mt++) {
                    mma_f16(acc[0][mt][nt], afr[mt], &bfrB[nt * 2]);
                    mma_f16(acc[1][mt][nt], afr[mt], &bfrC[nt * 2]);
                    mma_f16(acc[2][mt][nt], afr[mt], &bfrD[0][nt * 2]);
                    mma_f16(acc[2][mt][nt], afr[mt], &bfrD[1][nt * 2]);
                }
        }
        __syncthreads();
    }

    // ---- bias + negA hoist into smem (tiles dead; region beyond stage) ----
    float (*stage)[128][34] = (float (*)[128][34])smem_u16;   // [abar|bbar|cf][row][col]
    float* sbias = (float*)smem_u16 + 3 * 128 * 34;           // [4][32]
    if (tid < 128) {
        int a = tid >> 5, c = tid & 31;
        int nc = n0 + c;
        float v;
        if      (a == 0) v = bB[nc];
        else if (a == 1) v = bC[nc];
        else if (a == 2) v = bdt[nc];
        else             v = -__expf(Alog[nc]);
        sbias[a * 32 + c] = v;
    }
    __syncthreads();

    // ---- epilogue: transforms -> smem stage ----
    #pragma unroll
    for (int mt = 0; mt < 2; mt++) {
        #pragma unroll
        for (int nt = 0; nt < 2; nt++) {
            int lrow0 = wm * 32 + mt * 16 + g;
            int lcol0 = wn * 16 + nt * 8 + tg * 2;
            #pragma unroll
            for (int half = 0; half < 2; half++) {
                int lrow = lrow0 + half * 8;
                #pragma unroll
                for (int col = 0; col < 2; col++) {
                    int rg = half * 2 + col;
                    int lc = lcol0 + col;
                    float vB = acc[0][mt][nt][rg] + sbias[lc];
                    float vC = acc[1][mt][nt][rg] + sbias[32 + lc];
                    float t  = acc[2][mt][nt][rg] + sbias[64 + lc];
                    float dtv = (t > 20.f) ? t : log1pf(__expf(t));
                    float A = sbias[96 + lc];
                    stage[0][lrow][lc] = __expf(dtv * A);
                    stage[1][lrow][lc] = dtv * vB;
                    stage[2][lrow][lc] = vC;
                }
            }
        }
    }
    __syncthreads();

    // coalesced global writes: abar fp32 (float4), bbar/cf fp16 (half4 = uint2)
    #pragma unroll
    for (int j = 0; j < 4; j++) {               // abar: 1024 float4
        int i = tid + j * 256;
        int r = i >> 3, f = i & 7;
        float4 v;
        v.x = stage[0][r][f * 4 + 0];
        v.y = stage[0][r][f * 4 + 1];
        v.z = stage[0][r][f * 4 + 2];
        v.w = stage[0][r][f * 4 + 3];
        *(float4*)&g_abar[(m0 + r) * NN + n0 + f * 4] = v;
    }
    #pragma unroll
    for (int j = 0; j < 8; j++) {               // bbar/cf: 2 x 1024 half4
        int i = tid + j * 256;
        int a = i >> 10, rem = i & 1023, r = rem >> 3, f = rem & 7;
        union { __half2 b2[2]; uint2 u; } uu;
        uu.b2[0] = __floats2half2_rn(stage[1 + a][r][f * 4 + 0], stage[1 + a][r][f * 4 + 1]);
        uu.b2[1] = __floats2half2_rn(stage[1 + a][r][f * 4 + 2], stage[1 + a][r][f * 4 + 3]);
        __half* dst = a == 0 ? g_bbar2 : g_cf2;
        *(uint2*)&dst[(m0 + r) * NN + n0 + f * 4] = uu.u;
    }

    // fused scan pass 1: 8 chunks x 32 cols (all 256 threads)
    {
        int ch  = tid >> 5;           // local chunk 0..7
        int col = tid & 31;
        float h = 0.f, p = 1.f;
        #pragma unroll
        for (int s = 0; s < LCH; s++) {
            float a  = stage[0][ch * LCH + s][col];
            float bb = stage[1][ch * LCH + s][col];
            h = fmaf(a, h, bb);
            p *= a;
        }
        int bidx = m0 >> 11;                       // batch
        int chg  = ((m0 & (SS - 1)) >> 4) + ch;    // global chunk in batch
        int o = (bidx * NCH + chg) * NN + n0 + col;
        g_Aprod[o] = p;
        g_Hend[o]  = h;
    }
}

// ---------------- 3) chunk combine: 4 chunks/lane + warp Kogge-Stone --------------
// One warp per (b, n); lane handles chunks (4L .. 4L+3).
__global__ void scan_combine() {
    int t    = blockIdx.x * blockDim.x + threadIdx.x;   // 131072 threads = 4096 warps
    int lane = t & 31;
    int w    = t >> 5;
    int n    = w & (NN - 1);
    int b    = w >> 11;
    int base = (b * NCH + 4 * lane) * NN + n;
    float a0 = g_Aprod[base],          h0 = g_Hend[base];
    float a1 = g_Aprod[base + NN],     h1 = g_Hend[base + NN];
    float a2 = g_Aprod[base + 2 * NN], h2 = g_Hend[base + 2 * NN];
    float a3 = g_Aprod[base + 3 * NN], h3 = g_Hend[base + 3 * NN];
    float A01  = a1 * a0,  H01  = fmaf(a1, h0, h1);
    float A012 = a2 * A01, H012 = fmaf(a2, H01, h2);
    float A    = a3 * A012;
    float H    = fmaf(a3, H012, h3);
    #pragma unroll
    for (int d = 1; d < 32; d <<= 1) {
        float al = __shfl_up_sync(0xFFFFFFFFu, A, d);
        float hl = __shfl_up_sync(0xFFFFFFFFu, H, d);
        if (lane >= d) {
            H = fmaf(A, hl, H);
            A *= al;
        }
    }
    float hex = __shfl_up_sync(0xFFFFFFFFu, H, 1);      // exclusive over groups
    float hs = (lane == 0) ? 0.f : hex;
    g_Hstart[base]          = hs;
    g_Hstart[base + NN]     = fmaf(a0,   hs, h0);
    g_Hstart[base + 2 * NN] = fmaf(A01,  hs, H01);
    g_Hstart[base + 3 * NN] = fmaf(A012, hs, H012);
}

// ---------------- 4) scan pass 2: replay with correct h0, emit y (fp16), 4-wide ---
__global__ void scan_pass2() {
    int t  = blockIdx.x * blockDim.x + threadIdx.x;     // 131072 threads
    int n4 = (t & 511) << 2;
    int ch = (t >> 9) & (NCH - 1);
    int b  = t >> 16;
    int base = (b * SS + ch * LCH) * NN + n4;
    const float4* pa = (const float4*)(g_abar + base);
    const uint2*  pb = (const uint2*)(g_bbar2 + base);
    const uint2*  pc = (const uint2*)(g_cf2 + base);
    uint2* y = (uint2*)(g_y + base);
    float4 h = *(const float4*)&g_Hstart[(b * NCH + ch) * NN + n4];
    #pragma unroll
    for (int s = 0; s < LCH; s++) {
        float4 a = pa[s * (NN / 4)];
        union { uint2 u; __half2 b2[2]; } ub, uc, uy;
        ub.u = pb[s * (NN / 4)];
        uc.u = pc[s * (NN / 4)];
        float2 b0 = __half22float2(ub.b2[0]), b1 = __half22float2(ub.b2[1]);
        float2 c0 = __half22float2(uc.b2[0]), c1 = __half22float2(uc.b2[1]);
        h.x = fmaf(a.x, h.x, b0.x);
        h.y = fmaf(a.y, h.y, b0.y);
        h.z = fmaf(a.z, h.z, b1.x);
        h.w = fmaf(a.w, h.w, b1.y);
        uy.b2[0] = __floats2half2_rn(c0.x * h.x, c0.y * h.y);
        uy.b2[1] = __floats2half2_rn(c1.x * h.z, c1.y * h.w);
        y[s * (NN / 4)] = uy.u;
    }
}

// ---------------- 5) output projection GEMM + fused split-K reduction -------------
// out[m,d] = sum_n y[m,n] * W_out[d,n].  y single fp16; W 2-split (2 passes).
// Block: 64 (m) x 128 (d), 512 K per block; last CTA of each m-block reduces.
#define G2_SY_ELEMS (2*64*40)
#define G2_SW_ELEMS (2*2*128*40)
#define G2_SMEM ((G2_SY_ELEMS + G2_SW_ELEMS) * 2)

__global__ __launch_bounds__(256, 2)
void gemm2_out(const float* __restrict__ bout, float* __restrict__ out) {
    extern __shared__ unsigned short smem2_u16[];
    typedef unsigned short (*SYt)[64][40];
    typedef unsigned short (*SWot)[2][128][40];
    SYt  sY  = (SYt)smem2_u16;
    SWot sWo = (SWot)(smem2_u16 + G2_SY_ELEMS);
    __shared__ int red;

    const int tid  = threadIdx.x;
    const int warp = tid >> 5, lane = tid & 31;
    const int wm = warp >> 2, wn = warp & 3;
    const int m0 = blockIdx.x * 64;
    const int kp = blockIdx.y;              // 0..3
    const int g  = lane >> 2, tg = lane & 3;
    const int lm = lane >> 3, lr = lane & 7;

    float acc[2][4][4];
    #pragma unroll
    for (int a = 0; a < 2; a++)
        #pragma unroll
        for (int b = 0; b < 4; b++)
            #pragma unroll
            for (int c = 0; c < 4; c++) acc[a][b][c] = 0.f;

    auto load_tiles = [&](int buf, int kc) {
        const int kbase = kp * 512 + kc * 32;
        {                                           // y: 256 x 16B
            int i = tid;
            int r = i >> 2, w = i & 3;
            const __half* src = g_y + (m0 + r) * NN + kbase + w * 8;
            cp16(&sY[buf][r][w * 8], src);
        }
        #pragma unroll
        for (int j = 0; j < 4; j++) {               // W_out: 1024 x 16B
            int i = tid + j * 256;
            int sel = i >> 9, r = (i >> 2) & 127, w = i & 3;
            const __half* src = (sel ? g_Wol : g_Woh) + r * NN + kbase + w * 8;
            cp16(&sWo[buf][sel][r][w * 8], src);
        }
    };

    load_tiles(0, 0);
    CP_COMMIT();

    for (int kc = 0; kc < 16; kc++) {
        if (kc < 15) load_tiles((kc + 1) & 1, kc + 1);
        CP_COMMIT();
        CP_WAIT1();
        __syncthreads();
        const int buf = kc & 1;

        #pragma unroll
        for (int ks = 0; ks < 2; ks++) {
            const int kb = ks * 16;
            unsigned afr[2][4];
            #pragma unroll
            for (int mt = 0; mt < 2; mt++)
                ldsm4(afr[mt],
                      &sY[buf][wm * 32 + mt * 16 + (lm & 1) * 8 + lr][kb + (lm >> 1) * 8]);
            unsigned bfr[2][2][4];
            #pragma unroll
            for (int bs = 0; bs < 2; bs++)
                #pragma unroll
                for (int jp = 0; jp < 2; jp++)
                    ldsm4(bfr[bs][jp],
                          &sWo[buf][bs][wn * 32 + (jp * 2 + (lm >> 1)) * 8 + lr][kb + (lm & 1) * 8]);

            #pragma unroll
            for (int bs = 0; bs < 2; bs++) {        // yh*Wh + yh*Wl
                #pragma unroll
                for (int nt = 0; nt < 4; nt++) {
                    const unsigned* bp = &bfr[bs][nt >> 1][(nt & 1) * 2];
                    #pragma unroll
                    for (int mt = 0; mt < 2; mt++)
                        mma_f16(acc[mt][nt], afr[mt], bp);
                }
            }
        }
        __syncthreads();
    }

    // write deterministic split-K partials (float2 stores)
    float* part = g_part + kp * (MM * DD);
    #pragma unroll
    for (int mt = 0; mt < 2; mt++) {
        #pragma unroll
        for (int nt = 0; nt < 4; nt++) {
            int mr0 = m0 + wm * 32 + mt * 16 + g;
            int dc0 = wn * 32 + nt * 8 + tg * 2;
            #pragma unroll
            for (int half = 0; half < 2; half++) {
                int mr = mr0 + half * 8;
                float2 v;
                v.x = acc[mt][nt][half * 2 + 0];
                v.y = acc[mt][nt][half * 2 + 1];
                *(float2*)&part[mr * DD + dc0] = v;
            }
        }
    }

    // fused reduction: last CTA of this m-block sums the 4 partials + bias
    __threadfence();
    __syncthreads();
    if (tid == 0) red = atomicAdd(&g_cnt[blockIdx.x], 1);
    __syncthreads();
    if (red == 3) {
        const int MD = MM * DD;
        for (int j = tid; j < 64 * DD / 4; j += 256) {
            int idx = m0 * DD + j * 4;
            float4 v = *(const float4*)&bout[(j * 4) & (DD - 1)];
            float4 p0 = *(const float4*)&g_part[idx];
            float4 p1 = *(const float4*)&g_part[MD + idx];
            float4 p2 = *(const float4*)&g_part[2 * MD + idx];
            float4 p3 = *(const float4*)&g_part[3 * MD + idx];
            v.x += p0.x + p1.x + p2.x + p3.x;
            v.y += p0.y + p1.y + p2.y + p3.y;
            v.z += p0.z + p1.z + p2.z + p3.z;
            v.w += p0.w + p1.w + p2.w + p3.w;
            *(float4*)&out[idx] = v;
        }
        if (tid == 0) g_cnt[blockIdx.x] = 0;   // reset for next graph replay
    }
}

// ---------------- launch ----------------
extern "C" void kernel_launch(void* const* d_in, const int* in_sizes, int n_in,
                              void* d_out, int out_size) {
    const float* x     = (const float*)d_in[0];
    const float* W_B   = (const float*)d_in[1];
    const float* b_B   = (const float*)d_in[2];
    const float* W_C   = (const float*)d_in[3];
    const float* b_C   = (const float*)d_in[4];
    const float* W_dt  = (const float*)d_in[5];
    const float* b_dt  = (const float*)d_in[6];
    const float* A_log = (const float*)d_in[7];
    const float* W_out = (const float*)d_in[8];
    const float* b_out = (const float*)d_in[9];
    float* out = (float*)d_out;

    cudaFuncSetAttribute(gemm1_proj, cudaFuncAttributeMaxDynamicSharedMemorySize, G1_SMEM);
    cudaFuncSetAttribute(gemm2_out,  cudaFuncAttributeMaxDynamicSharedMemorySize, G2_SMEM);

    split_kernel<<<1536, 256>>>(x, W_B, W_C, W_dt, W_out);
    gemm1_proj<<<dim3(64, 32), 256, G1_SMEM>>>(b_B, b_C, b_dt, A_log);
    scan_combine<<<512, 256>>>();
    scan_pass2<<<512, 256>>>();
    gemm2_out<<<dim3(64, 4), 256, G2_SMEM>>>(b_out, out);
}

// round 16
// speedup vs baseline: 1.2367x; 1.0729x over previous
#include <cuda_runtime.h>
#include <cuda_fp16.h>
#include <math.h>

// Problem constants
#define BB   2
#define SS   2048
#define DD   128
#define NN   2048
#define MM   (BB * SS)          // 4096 rows
#define NCH  128                // scan chunks
#define LCH  16                 // steps per chunk (NCH*LCH == SS)

// ---------------- scratch (static device globals; no allocations) ----------------
__device__ __half g_xh[MM * DD];                                 // fp16 x (hi only)
__device__ __half g_Wh[3 * NN * DD], g_Wl[3 * NN * DD];          // fp16 split [W_B; W_C; W_dt]
__device__ __half g_Woh[DD * NN];                                // fp16 W_out (hi only)
__device__ float  g_abar[MM * NN];                               // exp(dt*A)   (fp32: scan-critical)
__device__ __half g_bbar2[MM * NN];                              // dt*B_feat   (fp16)
__device__ __half g_cf2  [MM * NN];                              // C_feat      (fp16)
__device__ __half g_y[MM * NN];                                  // y = c*h     (single fp16)
__device__ float g_Aprod [BB * NCH * NN];
__device__ float g_Hend  [BB * NCH * NN];
__device__ float g_Hstart[BB * NCH * NN];
__device__ float g_part[4 * MM * DD];                            // split-K partials
__device__ int   g_cnt[64];                                      // split-K completion counters

// ---------------- helpers ----------------
__device__ __forceinline__ void f16_split(float v, __half& h, __half& l) {
    h = __float2half_rn(v);
    l = __float2half_rn(v - __half2float(h));
}

__device__ __forceinline__ void mma_f16(float* c, const unsigned* a, const unsigned* b) {
    asm volatile(
        "mma.sync.aligned.m16n8k16.row.col.f32.f16.f16.f32 "
        "{%0,%1,%2,%3}, {%4,%5,%6,%7}, {%8,%9}, {%0,%1,%2,%3};\n"
        : "+f"(c[0]), "+f"(c[1]), "+f"(c[2]), "+f"(c[3])
        : "r"(a[0]), "r"(a[1]), "r"(a[2]), "r"(a[3]),
          "r"(b[0]), "r"(b[1]));
}

__device__ __forceinline__ void ldsm4(unsigned* r, const void* p) {
    unsigned a = (unsigned)__cvta_generic_to_shared(p);
    asm volatile("ldmatrix.sync.aligned.m8n8.x4.shared.b16 {%0,%1,%2,%3}, [%4];"
                 : "=r"(r[0]), "=r"(r[1]), "=r"(r[2]), "=r"(r[3]) : "r"(a));
}

__device__ __forceinline__ void cp16(void* smem_dst, const void* gmem_src) {
    unsigned s = (unsigned)__cvta_generic_to_shared(smem_dst);
    asm volatile("cp.async.cg.shared.global [%0], [%1], 16;\n" :: "r"(s), "l"(gmem_src));
}
#define CP_COMMIT() asm volatile("cp.async.commit_group;\n" ::: "memory")
#define CP_WAIT1()  asm volatile("cp.async.wait_group 1;\n" ::: "memory")

// ---------------- 0) split inputs: x/Wout -> fp16 hi; W -> fp16 hi/lo -------------
__global__ void split_kernel(const float* __restrict__ x,
                             const float* __restrict__ WB,
                             const float* __restrict__ WC,
                             const float* __restrict__ Wdt,
                             const float* __restrict__ Wout) {
    const int XE  = MM * DD;        // 524288
    const int WE  = NN * DD;        // 262144 per matrix
    const int WOE = DD * NN;        // 262144
    int i4 = (blockIdx.x * blockDim.x + threadIdx.x) * 4;

    if (i4 < XE) {                  // x: hi only
        float4 v = *(const float4*)&x[i4];
        union { __half2 b2[2]; uint2 u; } uh;
        uh.b2[0] = __floats2half2_rn(v.x, v.y);
        uh.b2[1] = __floats2half2_rn(v.z, v.w);
        *(uint2*)&g_xh[i4] = uh.u;
        return;
    }
    if (i4 >= XE + 3 * WE) {        // W_out: hi only
        int j = i4 - XE - 3 * WE;
        if (j >= WOE) return;
        float4 v = *(const float4*)&Wout[j];
        union { __half2 b2[2]; uint2 u; } uh;
        uh.b2[0] = __floats2half2_rn(v.x, v.y);
        uh.b2[1] = __floats2half2_rn(v.z, v.w);
        *(uint2*)&g_Woh[j] = uh.u;
        return;
    }
    int j = i4 - XE;
    const float* src = (j < WE) ? WB : ((j < 2 * WE) ? WC : Wdt);
    int off = j % WE;
    __half* dh = g_Wh + (j - off);
    __half* dl = g_Wl + (j - off);

    float4 v = *(const float4*)&src[off];
    __half h0, l0, h1, l1, h2, l2, h3, l3;
    f16_split(v.x, h0, l0); f16_split(v.y, h1, l1);
    f16_split(v.z, h2, l2); f16_split(v.w, h3, l3);
    union { __half2 b2[2]; uint2 u; } uh, ul;
    uh.b2[0] = __halves2half2(h0, h1); uh.b2[1] = __halves2half2(h2, h3);
    ul.b2[0] = __halves2half2(l0, l1); ul.b2[1] = __halves2half2(l2, l3);
    *(uint2*)&dh[off] = uh.u;
    *(uint2*)&dl[off] = ul.u;
}

// ---------------- 1) fused projection GEMM + featurizer + chunk-scan pass 1 -------
// Block tile: 128 (m) x 32 (n) per matrix, K=128 in 4 chunks of 32, cp.async 2-buf.
// 2 CTAs/SM (co-resident CTA hides serial epilogue phases — proven critical).
// x single fp16 (hi). Passes: hh for W_B/W_C; (hh, hl) for W_dt.
// An m-block = 8 scan chunks (LCH=16); scan pass-1 in-CTA from the smem stage.
#define G1_SX_ELEMS (2*128*40)           // [buf][row][pitch40] shorts (x hi only)
#define G1_SW_ELEMS (2*3*2*32*40)        // [buf][mat][sel][row][pitch40] shorts
#define G1_TILES ((G1_SX_ELEMS + G1_SW_ELEMS) * 2)          // 51,200 B
#define G1_SMEM  52736                                      // stage (52,736 B) > tiles

__global__ __launch_bounds__(256, 2)
void gemm1_proj(const float* __restrict__ bB, const float* __restrict__ bC,
                const float* __restrict__ bdt, const float* __restrict__ Alog) {
    extern __shared__ unsigned short smem_u16[];
    typedef unsigned short (*SXt)[128][40];
    typedef unsigned short (*SWt)[3][2][32][40];
    SXt sX = (SXt)smem_u16;
    SWt sW = (SWt)(smem_u16 + G1_SX_ELEMS);

    const int tid  = threadIdx.x;
    const int warp = tid >> 5, lane = tid & 31;
    const int wm = warp >> 1, wn = warp & 1;
    const int m0 = blockIdx.y * 128;
    const int n0 = blockIdx.x * 32;
    const int g  = lane >> 2, tg = lane & 3;
    const int lm = lane >> 3, lr = lane & 7;     // ldmatrix lane decomposition

    float acc[3][2][2][4];
    #pragma unroll
    for (int a = 0; a < 3; a++)
        #pragma unroll
        for (int b = 0; b < 2; b++)
            #pragma unroll
            for (int c = 0; c < 2; c++)
                #pragma unroll
                for (int d = 0; d < 4; d++) acc[a][b][c][d] = 0.f;

    // async tile loader for k-chunk kc into buffer buf
    // W combos loaded: (B,h) (C,h) (dt,h) (dt,l)
    auto load_tiles = [&](int buf, int kc) {
        #pragma unroll
        for (int j = 0; j < 2; j++) {               // x: 512 x 16B
            int i = tid + j * 256;
            int r = (i >> 2) & 127, w = i & 3;
            const __half* src = g_xh + (m0 + r) * DD + kc * 32 + w * 8;
            cp16(&sX[buf][r][w * 8], src);
        }
        #pragma unroll
        for (int j = 0; j < 2; j++) {               // W: 512 x 16B
            int i = tid + j * 256;
            int combo = i >> 7, r = (i >> 2) & 31, w = i & 3;
            int mat = (combo < 3) ? combo : 2;
            int sel = (combo == 3) ? 1 : 0;
            const __half* src = (sel ? g_Wl : g_Wh) + (mat * NN + n0 + r) * DD + kc * 32 + w * 8;
            cp16(&sW[buf][mat][sel][r][w * 8], src);
        }
    };

    load_tiles(0, 0);
    CP_COMMIT();

    for (int kc = 0; kc < 4; kc++) {
        if (kc < 3) load_tiles((kc + 1) & 1, kc + 1);
        CP_COMMIT();                 // real group, or empty group on last iter
        CP_WAIT1();                  // forces chunk-kc group completion
        __syncthreads();
        const int buf = kc & 1;

        #pragma unroll
        for (int ks = 0; ks < 2; ks++) {
            const int kb = ks * 16;
            // hoisted A fragments (2 LDSM)
            unsigned afr[2][4];
            #pragma unroll
            for (int mt = 0; mt < 2; mt++)
                ldsm4(afr[mt],
                      &sX[buf][wm * 32 + mt * 16 + (lm & 1) * 8 + lr][kb + (lm >> 1) * 8]);
            // hoisted B fragments (4 LDSM): B.h, C.h, dt.h, dt.l
            unsigned bfrB[4], bfrC[4], bfrD[2][4];
            ldsm4(bfrB,    &sW[buf][0][0][wn * 16 + (lm >> 1) * 8 + lr][kb + (lm & 1) * 8]);
            ldsm4(bfrC,    &sW[buf][1][0][wn * 16 + (lm >> 1) * 8 + lr][kb + (lm & 1) * 8]);
            ldsm4(bfrD[0], &sW[buf][2][0][wn * 16 + (lm >> 1) * 8 + lr][kb + (lm & 1) * 8]);
            ldsm4(bfrD[1], &sW[buf][2][1][wn * 16 + (lm >> 1) * 8 + lr][kb + (lm & 1) * 8]);

            // B, C: hh; dt: hh + hl
            #pragma unroll
            for (int nt = 0; nt < 2; nt++)
                #pragma unroll
                for (int mt = 0; mt < 2; mt++) {
                    mma_f16(acc[0][mt][nt], afr[mt], &bfrB[nt * 2]);
                    mma_f16(acc[1][mt][nt], afr[mt], &bfrC[nt * 2]);
                    mma_f16(acc[2][mt][nt], afr[mt], &bfrD[0][nt * 2]);
                    mma_f16(acc[2][mt][nt], afr[mt], &bfrD[1][nt * 2]);
                }
        }
        __syncthreads();
    }

    // ---- bias + negA hoist into smem (tiles dead; region beyond stage) ----
    float (*stage)[128][34] = (float (*)[128][34])smem_u16;   // [abar|bbar|cf][row][col]
    float* sbias = (float*)smem_u16 + 3 * 128 * 34;           // [4][32]
    if (tid < 128) {
        int a = tid >> 5, c = tid & 31;
        int nc = n0 + c;
        float v;
        if      (a == 0) v = bB[nc];
        else if (a == 1) v = bC[nc];
        else if (a == 2) v = bdt[nc];
        else             v = -__expf(Alog[nc]);
        sbias[a * 32 + c] = v;
    }
    __syncthreads();

    // ---- epilogue: transforms -> smem stage ----
    #pragma unroll
    for (int mt = 0; mt < 2; mt++) {
        #pragma unroll
        for (int nt = 0; nt < 2; nt++) {
            int lrow0 = wm * 32 + mt * 16 + g;
            int lcol0 = wn * 16 + nt * 8 + tg * 2;
            #pragma unroll
            for (int half = 0; half < 2; half++) {
                int lrow = lrow0 + half * 8;
                #pragma unroll
                for (int col = 0; col < 2; col++) {
                    int rg = half * 2 + col;
                    int lc = lcol0 + col;
                    float vB = acc[0][mt][nt][rg] + sbias[lc];
                    float vC = acc[1][mt][nt][rg] + sbias[32 + lc];
                    float t  = acc[2][mt][nt][rg] + sbias[64 + lc];
                    float dtv = (t > 20.f) ? t : log1pf(__expf(t));
                    float A = sbias[96 + lc];
                    stage[0][lrow][lc] = __expf(dtv * A);
                    stage[1][lrow][lc] = dtv * vB;
                    stage[2][lrow][lc] = vC;
                }
            }
        }
    }
    __syncthreads();

    // coalesced global writes: abar fp32 (float4), bbar/cf fp16 (half4 = uint2)
    #pragma unroll
    for (int j = 0; j < 4; j++) {               // abar: 1024 float4
        int i = tid + j * 256;
        int r = i >> 3, f = i & 7;
        float4 v;
        v.x = stage[0][r][f * 4 + 0];
        v.y = stage[0][r][f * 4 + 1];
        v.z = stage[0][r][f * 4 + 2];
        v.w = stage[0][r][f * 4 + 3];
        *(float4*)&g_abar[(m0 + r) * NN + n0 + f * 4] = v;
    }
    #pragma unroll
    for (int j = 0; j < 8; j++) {               // bbar/cf: 2 x 1024 half4
        int i = tid + j * 256;
        int a = i >> 10, rem = i & 1023, r = rem >> 3, f = rem & 7;
        union { __half2 b2[2]; uint2 u; } uu;
        uu.b2[0] = __floats2half2_rn(stage[1 + a][r][f * 4 + 0], stage[1 + a][r][f * 4 + 1]);
        uu.b2[1] = __floats2half2_rn(stage[1 + a][r][f * 4 + 2], stage[1 + a][r][f * 4 + 3]);
        __half* dst = a == 0 ? g_bbar2 : g_cf2;
        *(uint2*)&dst[(m0 + r) * NN + n0 + f * 4] = uu.u;
    }

    // fused scan pass 1: 8 chunks x 32 cols (all 256 threads)
    {
        int ch  = tid >> 5;           // local chunk 0..7
        int col = tid & 31;
        float h = 0.f, p = 1.f;
        #pragma unroll
        for (int s = 0; s < LCH; s++) {
            float a  = stage[0][ch * LCH + s][col];
            float bb = stage[1][ch * LCH + s][col];
            h = fmaf(a, h, bb);
            p *= a;
        }
        int bidx = m0 >> 11;                       // batch
        int chg  = ((m0 & (SS - 1)) >> 4) + ch;    // global chunk in batch
        int o = (bidx * NCH + chg) * NN + n0 + col;
        g_Aprod[o] = p;
        g_Hend[o]  = h;
    }
}

// ---------------- 3) chunk combine: 4 chunks/lane + warp Kogge-Stone --------------
// One warp per (b, n); lane handles chunks (4L .. 4L+3).
__global__ void scan_combine() {
    int t    = blockIdx.x * blockDim.x + threadIdx.x;   // 131072 threads = 4096 warps
    int lane = t & 31;
    int w    = t >> 5;
    int n    = w & (NN - 1);
    int b    = w >> 11;
    int base = (b * NCH + 4 * lane) * NN + n;
    float a0 = g_Aprod[base],          h0 = g_Hend[base];
    float a1 = g_Aprod[base + NN],     h1 = g_Hend[base + NN];
    float a2 = g_Aprod[base + 2 * NN], h2 = g_Hend[base + 2 * NN];
    float a3 = g_Aprod[base + 3 * NN], h3 = g_Hend[base + 3 * NN];
    float A01  = a1 * a0,  H01  = fmaf(a1, h0, h1);
    float A012 = a2 * A01, H012 = fmaf(a2, H01, h2);
    float A    = a3 * A012;
    float H    = fmaf(a3, H012, h3);
    #pragma unroll
    for (int d = 1; d < 32; d <<= 1) {
        float al = __shfl_up_sync(0xFFFFFFFFu, A, d);
        float hl = __shfl_up_sync(0xFFFFFFFFu, H, d);
        if (lane >= d) {
            H = fmaf(A, hl, H);
            A *= al;
        }
    }
    float hex = __shfl_up_sync(0xFFFFFFFFu, H, 1);      // exclusive over groups
    float hs = (lane == 0) ? 0.f : hex;
    g_Hstart[base]          = hs;
    g_Hstart[base + NN]     = fmaf(a0,   hs, h0);
    g_Hstart[base + 2 * NN] = fmaf(A01,  hs, H01);
    g_Hstart[base + 3 * NN] = fmaf(A012, hs, H012);
}

// ---------------- 4) scan pass 2: replay with correct h0, emit y (fp16), 4-wide ---
__global__ void scan_pass2() {
    int t  = blockIdx.x * blockDim.x + threadIdx.x;     // 131072 threads
    int n4 = (t & 511) << 2;
    int ch = (t >> 9) & (NCH - 1);
    int b  = t >> 16;
    int base = (b * SS + ch * LCH) * NN + n4;
    const float4* pa = (const float4*)(g_abar + base);
    const uint2*  pb = (const uint2*)(g_bbar2 + base);
    const uint2*  pc = (const uint2*)(g_cf2 + base);
    uint2* y = (uint2*)(g_y + base);
    float4 h = *(const float4*)&g_Hstart[(b * NCH + ch) * NN + n4];
    #pragma unroll
    for (int s = 0; s < LCH; s++) {
        float4 a = pa[s * (NN / 4)];
        union { uint2 u; __half2 b2[2]; } ub, uc, uy;
        ub.u = pb[s * (NN / 4)];
        uc.u = pc[s * (NN / 4)];
        float2 b0 = __half22float2(ub.b2[0]), b1 = __half22float2(ub.b2[1]);
        float2 c0 = __half22float2(uc.b2[0]), c1 = __half22float2(uc.b2[1]);
        h.x = fmaf(a.x, h.x, b0.x);
        h.y = fmaf(a.y, h.y, b0.y);
        h.z = fmaf(a.z, h.z, b1.x);
        h.w = fmaf(a.w, h.w, b1.y);
        uy.b2[0] = __floats2half2_rn(c0.x * h.x, c0.y * h.y);
        uy.b2[1] = __floats2half2_rn(c1.x * h.z, c1.y * h.w);
        y[s * (NN / 4)] = uy.u;
    }
}

// ---------------- 5) output projection GEMM + fused split-K reduction -------------
// out[m,d] = sum_n y[m,n] * W_out[d,n].  y and W_out single fp16 (1 pass).
// Block: 64 (m) x 128 (d), 512 K per block; last CTA of each m-block reduces.
#define G2_SY_ELEMS (2*64*40)
#define G2_SW_ELEMS (2*128*40)
#define G2_SMEM ((G2_SY_ELEMS + G2_SW_ELEMS) * 2)

__global__ __launch_bounds__(256, 2)
void gemm2_out(const float* __restrict__ bout, float* __restrict__ out) {
    extern __shared__ unsigned short smem2_u16[];
    typedef unsigned short (*SYt)[64][40];
    typedef unsigned short (*SWot)[128][40];
    SYt  sY  = (SYt)smem2_u16;
    SWot sWo = (SWot)(smem2_u16 + G2_SY_ELEMS);
    __shared__ int red;

    const int tid  = threadIdx.x;
    const int warp = tid >> 5, lane = tid & 31;
    const int wm = warp >> 2, wn = warp & 3;
    const int m0 = blockIdx.x * 64;
    const int kp = blockIdx.y;              // 0..3
    const int g  = lane >> 2, tg = lane & 3;
    const int lm = lane >> 3, lr = lane & 7;

    float acc[2][4][4];
    #pragma unroll
    for (int a = 0; a < 2; a++)
        #pragma unroll
        for (int b = 0; b < 4; b++)
            #pragma unroll
            for (int c = 0; c < 4; c++) acc[a][b][c] = 0.f;

    auto load_tiles = [&](int buf, int kc) {
        const int kbase = kp * 512 + kc * 32;
        {                                           // y: 256 x 16B
            int i = tid;
            int r = i >> 2, w = i & 3;
            const __half* src = g_y + (m0 + r) * NN + kbase + w * 8;
            cp16(&sY[buf][r][w * 8], src);
        }
        #pragma unroll
        for (int j = 0; j < 2; j++) {               // W_out: 512 x 16B
            int i = tid + j * 256;
            int r = (i >> 2) & 127, w = i & 3;
            const __half* src = g_Woh + r * NN + kbase + w * 8;
            cp16(&sWo[buf][r][w * 8], src);
        }
    };

    load_tiles(0, 0);
    CP_COMMIT();

    for (int kc = 0; kc < 16; kc++) {
        if (kc < 15) load_tiles((kc + 1) & 1, kc + 1);
        CP_COMMIT();
        CP_WAIT1();
        __syncthreads();
        const int buf = kc & 1;

        #pragma unroll
        for (int ks = 0; ks < 2; ks++) {
            const int kb = ks * 16;
            unsigned afr[2][4];
            #pragma unroll
            for (int mt = 0; mt < 2; mt++)
                ldsm4(afr[mt],
                      &sY[buf][wm * 32 + mt * 16 + (lm & 1) * 8 + lr][kb + (lm >> 1) * 8]);
            unsigned bfr[2][4];
            #pragma unroll
            for (int jp = 0; jp < 2; jp++)
                ldsm4(bfr[jp],
                      &sWo[buf][wn * 32 + (jp * 2 + (lm >> 1)) * 8 + lr][kb + (lm & 1) * 8]);

            #pragma unroll
            for (int nt = 0; nt < 4; nt++) {
                const unsigned* bp = &bfr[nt >> 1][(nt & 1) * 2];
                #pragma unroll
                for (int mt = 0; mt < 2; mt++)
                    mma_f16(acc[mt][nt], afr[mt], bp);
            }
        }
        __syncthreads();
    }

    // write deterministic split-K partials (float2 stores)
    float* part = g_part + kp * (MM * DD);
    #pragma unroll
    for (int mt = 0; mt < 2; mt++) {
        #pragma unroll
        for (int nt = 0; nt < 4; nt++) {
            int mr0 = m0 + wm * 32 + mt * 16 + g;
            int dc0 = wn * 32 + nt * 8 + tg * 2;
            #pragma unroll
            for (int half = 0; half < 2; half++) {
                int mr = mr0 + half * 8;
                float2 v;
                v.x = acc[mt][nt][half * 2 + 0];
                v.y = acc[mt][nt][half * 2 + 1];
                *(float2*)&part[mr * DD + dc0] = v;
            }
        }
    }

    // fused reduction: last CTA of this m-block sums the 4 partials + bias
    __threadfence();
    __syncthreads();
    if (tid == 0) red = atomicAdd(&g_cnt[blockIdx.x], 1);
    __syncthreads();
    if (red == 3) {
        const int MD = MM * DD;
        for (int j = tid; j < 64 * DD / 4; j += 256) {
            int idx = m0 * DD + j * 4;
            float4 v = *(const float4*)&bout[(j * 4) & (DD - 1)];
            float4 p0 = *(const float4*)&g_part[idx];
            float4 p1 = *(const float4*)&g_part[MD + idx];
            float4 p2 = *(const float4*)&g_part[2 * MD + idx];
            float4 p3 = *(const float4*)&g_part[3 * MD + idx];
            v.x += p0.x + p1.x + p2.x + p3.x;
            v.y += p0.y + p1.y + p2.y + p3.y;
            v.z += p0.z + p1.z + p2.z + p3.z;
            v.w += p0.w + p1.w + p2.w + p3.w;
            *(float4*)&out[idx] = v;
        }
        if (tid == 0) g_cnt[blockIdx.x] = 0;   // reset for next graph replay
    }
}

// ---------------- launch ----------------
extern "C" void kernel_launch(void* const* d_in, const int* in_sizes, int n_in,
                              void* d_out, int out_size) {
    const float* x     = (const float*)d_in[0];
    const float* W_B   = (const float*)d_in[1];
    const float* b_B   = (const float*)d_in[2];
    const float* W_C   = (const float*)d_in[3];
    const float* b_C   = (const float*)d_in[4];
    const float* W_dt  = (const float*)d_in[5];
    const float* b_dt  = (const float*)d_in[6];
    const float* A_log = (const float*)d_in[7];
    const float* W_out = (const float*)d_in[8];
    const float* b_out = (const float*)d_in[9];
    float* out = (float*)d_out;

    cudaFuncSetAttribute(gemm1_proj, cudaFuncAttributeMaxDynamicSharedMemorySize, G1_SMEM);
    cudaFuncSetAttribute(gemm2_out,  cudaFuncAttributeMaxDynamicSharedMemorySize, G2_SMEM);

    split_kernel<<<1536, 256>>>(x, W_B, W_C, W_dt, W_out);
    gemm1_proj<<<dim3(64, 32), 256, G1_SMEM>>>(b_B, b_C, b_dt, A_log);
    scan_combine<<<512, 256>>>();
    scan_pass2<<<512, 256>>>();
    gemm2_out<<<dim3(64, 4), 256, G2_SMEM>>>(b_out, out);
}

// round 17
// speedup vs baseline: 1.2949x; 1.0471x over previous
#include <cuda_runtime.h>
#include <cuda_fp16.h>
#include <math.h>

// Problem constants
#define BB   2
#define SS   2048
#define DD   128
#define NN   2048
#define MM   (BB * SS)          // 4096 rows
#define NCH  128                // scan chunks
#define LCH  16                 // steps per chunk (NCH*LCH == SS)

// ---------------- scratch (static device globals; no allocations) ----------------
__device__ __half g_xh[MM * DD];                                 // fp16 x (hi only)
__device__ __half g_Wh[3 * NN * DD], g_Wl[3 * NN * DD];          // fp16 split [W_B; W_C; W_dt]
__device__ __half g_Woh[DD * NN];                                // fp16 W_out (hi only)
__device__ float  g_abar[MM * NN];                               // exp(dt*A)   (fp32: scan-critical)
__device__ __half g_bbar2[MM * NN];                              // dt*B_feat   (fp16)
__device__ __half g_cf2  [MM * NN];                              // C_feat      (fp16)
__device__ __half g_y[MM * NN];                                  // y = c*h     (single fp16)
__device__ float g_Aprod [BB * NCH * NN];
__device__ float g_Hend  [BB * NCH * NN];
__device__ float g_Hstart[BB * NCH * NN];
__device__ float g_part[4 * MM * DD];                            // split-K partials
__device__ int   g_cnt[64];                                      // split-K completion counters

// ---------------- helpers ----------------
__device__ __forceinline__ void f16_split(float v, __half& h, __half& l) {
    h = __float2half_rn(v);
    l = __float2half_rn(v - __half2float(h));
}

__device__ __forceinline__ void mma_f16(float* c, const unsigned* a, const unsigned* b) {
    asm volatile(
        "mma.sync.aligned.m16n8k16.row.col.f32.f16.f16.f32 "
        "{%0,%1,%2,%3}, {%4,%5,%6,%7}, {%8,%9}, {%0,%1,%2,%3};\n"
        : "+f"(c[0]), "+f"(c[1]), "+f"(c[2]), "+f"(c[3])
        : "r"(a[0]), "r"(a[1]), "r"(a[2]), "r"(a[3]),
          "r"(b[0]), "r"(b[1]));
}

__device__ __forceinline__ void ldsm4(unsigned* r, const void* p) {
    unsigned a = (unsigned)__cvta_generic_to_shared(p);
    asm volatile("ldmatrix.sync.aligned.m8n8.x4.shared.b16 {%0,%1,%2,%3}, [%4];"
                 : "=r"(r[0]), "=r"(r[1]), "=r"(r[2]), "=r"(r[3]) : "r"(a));
}

__device__ __forceinline__ void cp16(void* smem_dst, const void* gmem_src) {
    unsigned s = (unsigned)__cvta_generic_to_shared(smem_dst);
    asm volatile("cp.async.cg.shared.global [%0], [%1], 16;\n" :: "r"(s), "l"(gmem_src));
}
#define CP_COMMIT() asm volatile("cp.async.commit_group;\n" ::: "memory")
#define CP_WAIT1()  asm volatile("cp.async.wait_group 1;\n" ::: "memory")

// ---------------- 0) split inputs: x/Wout -> fp16 hi; W -> fp16 hi/lo -------------
__global__ void split_kernel(const float* __restrict__ x,
                             const float* __restrict__ WB,
                             const float* __restrict__ WC,
                             const float* __restrict__ Wdt,
                             const float* __restrict__ Wout) {
    const int XE  = MM * DD;        // 524288
    const int WE  = NN * DD;        // 262144 per matrix
    const int WOE = DD * NN;        // 262144
    int i4 = (blockIdx.x * blockDim.x + threadIdx.x) * 4;

    if (i4 < XE) {                  // x: hi only
        float4 v = *(const float4*)&x[i4];
        union { __half2 b2[2]; uint2 u; } uh;
        uh.b2[0] = __floats2half2_rn(v.x, v.y);
        uh.b2[1] = __floats2half2_rn(v.z, v.w);
        *(uint2*)&g_xh[i4] = uh.u;
        return;
    }
    if (i4 >= XE + 3 * WE) {        // W_out: hi only
        int j = i4 - XE - 3 * WE;
        if (j >= WOE) return;
        float4 v = *(const float4*)&Wout[j];
        union { __half2 b2[2]; uint2 u; } uh;
        uh.b2[0] = __floats2half2_rn(v.x, v.y);
        uh.b2[1] = __floats2half2_rn(v.z, v.w);
        *(uint2*)&g_Woh[j] = uh.u;
        return;
    }
    int j = i4 - XE;
    const float* src = (j < WE) ? WB : ((j < 2 * WE) ? WC : Wdt);
    int off = j % WE;
    __half* dh = g_Wh + (j - off);
    __half* dl = g_Wl + (j - off);

    float4 v = *(const float4*)&src[off];
    __half h0, l0, h1, l1, h2, l2, h3, l3;
    f16_split(v.x, h0, l0); f16_split(v.y, h1, l1);
    f16_split(v.z, h2, l2); f16_split(v.w, h3, l3);
    union { __half2 b2[2]; uint2 u; } uh, ul;
    uh.b2[0] = __halves2half2(h0, h1); uh.b2[1] = __halves2half2(h2, h3);
    ul.b2[0] = __halves2half2(l0, l1); ul.b2[1] = __halves2half2(l2, l3);
    *(uint2*)&dh[off] = uh.u;
    *(uint2*)&dl[off] = ul.u;
}

// ---------------- 1) fused projection GEMM + featurizer + chunk-scan pass 1 -------
// Block tile: 128 (m) x 32 (n) per matrix, K=128 in 4 chunks of 32, cp.async 2-buf.
// 2 CTAs/SM (co-resident CTA hides serial epilogue phases — proven critical).
// x single fp16 (hi). Passes: hh for W_B/W_C; (hh, hl) for W_dt.
// An m-block = 8 scan chunks (LCH=16); scan pass-1 in-CTA from the smem stage.
#define G1_SX_ELEMS (2*128*40)           // [buf][row][pitch40] shorts (x hi only)
#define G1_SW_ELEMS (2*3*2*32*40)        // [buf][mat][sel][row][pitch40] shorts
#define G1_TILES ((G1_SX_ELEMS + G1_SW_ELEMS) * 2)          // 51,200 B
#define G1_SMEM  52736                                      // stage (52,736 B) > tiles

__global__ __launch_bounds__(256, 2)
void gemm1_proj(const float* __restrict__ bB, const float* __restrict__ bC,
                const float* __restrict__ bdt, const float* __restrict__ Alog) {
    extern __shared__ unsigned short smem_u16[];
    typedef unsigned short (*SXt)[128][40];
    typedef unsigned short (*SWt)[3][2][32][40];
    SXt sX = (SXt)smem_u16;
    SWt sW = (SWt)(smem_u16 + G1_SX_ELEMS);

    const int tid  = threadIdx.x;
    const int warp = tid >> 5, lane = tid & 31;
    const int wm = warp >> 1, wn = warp & 1;
    const int m0 = blockIdx.y * 128;
    const int n0 = blockIdx.x * 32;
    const int g  = lane >> 2, tg = lane & 3;
    const int lm = lane >> 3, lr = lane & 7;     // ldmatrix lane decomposition

    float acc[3][2][2][4];
    #pragma unroll
    for (int a = 0; a < 3; a++)
        #pragma unroll
        for (int b = 0; b < 2; b++)
            #pragma unroll
            for (int c = 0; c < 2; c++)
                #pragma unroll
                for (int d = 0; d < 4; d++) acc[a][b][c][d] = 0.f;

    // async tile loader for k-chunk kc into buffer buf
    // W combos loaded: (B,h) (C,h) (dt,h) (dt,l)
    auto load_tiles = [&](int buf, int kc) {
        #pragma unroll
        for (int j = 0; j < 2; j++) {               // x: 512 x 16B
            int i = tid + j * 256;
            int r = (i >> 2) & 127, w = i & 3;
            const __half* src = g_xh + (m0 + r) * DD + kc * 32 + w * 8;
            cp16(&sX[buf][r][w * 8], src);
        }
        #pragma unroll
        for (int j = 0; j < 2; j++) {               // W: 512 x 16B
            int i = tid + j * 256;
            int combo = i >> 7, r = (i >> 2) & 31, w = i & 3;
            int mat = (combo < 3) ? combo : 2;
            int sel = (combo == 3) ? 1 : 0;
            const __half* src = (sel ? g_Wl : g_Wh) + (mat * NN + n0 + r) * DD + kc * 32 + w * 8;
            cp16(&sW[buf][mat][sel][r][w * 8], src);
        }
    };

    load_tiles(0, 0);
    CP_COMMIT();

    for (int kc = 0; kc < 4; kc++) {
        if (kc < 3) load_tiles((kc + 1) & 1, kc + 1);
        CP_COMMIT();                 // real group, or empty group on last iter
        CP_WAIT1();                  // forces chunk-kc group completion
        __syncthreads();
        const int buf = kc & 1;

        #pragma unroll
        for (int ks = 0; ks < 2; ks++) {
            const int kb = ks * 16;
            // hoisted A fragments (2 LDSM)
            unsigned afr[2][4];
            #pragma unroll
            for (int mt = 0; mt < 2; mt++)
                ldsm4(afr[mt],
                      &sX[buf][wm * 32 + mt * 16 + (lm & 1) * 8 + lr][kb + (lm >> 1) * 8]);
            // hoisted B fragments (4 LDSM): B.h, C.h, dt.h, dt.l
            unsigned bfrB[4], bfrC[4], bfrD[2][4];
            ldsm4(bfrB,    &sW[buf][0][0][wn * 16 + (lm >> 1) * 8 + lr][kb + (lm & 1) * 8]);
            ldsm4(bfrC,    &sW[buf][1][0][wn * 16 + (lm >> 1) * 8 + lr][kb + (lm & 1) * 8]);
            ldsm4(bfrD[0], &sW[buf][2][0][wn * 16 + (lm >> 1) * 8 + lr][kb + (lm & 1) * 8]);
            ldsm4(bfrD[1], &sW[buf][2][1][wn * 16 + (lm >> 1) * 8 + lr][kb + (lm & 1) * 8]);

            // B, C: hh; dt: hh + hl
            #pragma unroll
            for (int nt = 0; nt < 2; nt++)
                #pragma unroll
                for (int mt = 0; mt < 2; mt++) {
                    mma_f16(acc[0][mt][nt], afr[mt], &bfrB[nt * 2]);
                    mma_f16(acc[1][mt][nt], afr[mt], &bfrC[nt * 2]);
                    mma_f16(acc[2][mt][nt], afr[mt], &bfrD[0][nt * 2]);
                    mma_f16(acc[2][mt][nt], afr[mt], &bfrD[1][nt * 2]);
                }
        }
        __syncthreads();
    }

    // ---- bias + negA hoist into smem (tiles dead; region beyond stage) ----
    float (*stage)[128][34] = (float (*)[128][34])smem_u16;   // [abar|bbar|cf][row][col]
    float* sbias = (float*)smem_u16 + 3 * 128 * 34;           // [4][32]
    if (tid < 128) {
        int a = tid >> 5, c = tid & 31;
        int nc = n0 + c;
        float v;
        if      (a == 0) v = bB[nc];
        else if (a == 1) v = bC[nc];
        else if (a == 2) v = bdt[nc];
        else             v = -__expf(Alog[nc]);
        sbias[a * 32 + c] = v;
    }
    __syncthreads();

    // ---- epilogue: transforms -> smem stage (fast softplus: MUFU log/exp) ----
    #pragma unroll
    for (int mt = 0; mt < 2; mt++) {
        #pragma unroll
        for (int nt = 0; nt < 2; nt++) {
            int lrow0 = wm * 32 + mt * 16 + g;
            int lcol0 = wn * 16 + nt * 8 + tg * 2;
            #pragma unroll
            for (int half = 0; half < 2; half++) {
                int lrow = lrow0 + half * 8;
                #pragma unroll
                for (int col = 0; col < 2; col++) {
                    int rg = half * 2 + col;
                    int lc = lcol0 + col;
                    float vB = acc[0][mt][nt][rg] + sbias[lc];
                    float vC = acc[1][mt][nt][rg] + sbias[32 + lc];
                    float t  = acc[2][mt][nt][rg] + sbias[64 + lc];
                    float dtv = (t > 15.f) ? t : __logf(1.f + __expf(t));
                    float A = sbias[96 + lc];
                    stage[0][lrow][lc] = __expf(dtv * A);
                    stage[1][lrow][lc] = dtv * vB;
                    stage[2][lrow][lc] = vC;
                }
            }
        }
    }
    __syncthreads();

    // coalesced global writes: abar fp32 (float4), bbar/cf fp16 (half4 = uint2)
    #pragma unroll
    for (int j = 0; j < 4; j++) {               // abar: 1024 float4
        int i = tid + j * 256;
        int r = i >> 3, f = i & 7;
        float4 v;
        v.x = stage[0][r][f * 4 + 0];
        v.y = stage[0][r][f * 4 + 1];
        v.z = stage[0][r][f * 4 + 2];
        v.w = stage[0][r][f * 4 + 3];
        *(float4*)&g_abar[(m0 + r) * NN + n0 + f * 4] = v;
    }
    #pragma unroll
    for (int j = 0; j < 8; j++) {               // bbar/cf: 2 x 1024 half4
        int i = tid + j * 256;
        int a = i >> 10, rem = i & 1023, r = rem >> 3, f = rem & 7;
        union { __half2 b2[2]; uint2 u; } uu;
        uu.b2[0] = __floats2half2_rn(stage[1 + a][r][f * 4 + 0], stage[1 + a][r][f * 4 + 1]);
        uu.b2[1] = __floats2half2_rn(stage[1 + a][r][f * 4 + 2], stage[1 + a][r][f * 4 + 3]);
        __half* dst = a == 0 ? g_bbar2 : g_cf2;
        *(uint2*)&dst[(m0 + r) * NN + n0 + f * 4] = uu.u;
    }

    // fused scan pass 1: 8 chunks x 32 cols (all 256 threads)
    {
        int ch  = tid >> 5;           // local chunk 0..7
        int col = tid & 31;
        float h = 0.f, p = 1.f;
        #pragma unroll
        for (int s = 0; s < LCH; s++) {
            float a  = stage[0][ch * LCH + s][col];
            float bb = stage[1][ch * LCH + s][col];
            h = fmaf(a, h, bb);
            p *= a;
        }
        int bidx = m0 >> 11;                       // batch
        int chg  = ((m0 & (SS - 1)) >> 4) + ch;    // global chunk in batch
        int o = (bidx * NCH + chg) * NN + n0 + col;
        g_Aprod[o] = p;
        g_Hend[o]  = h;
    }
}

// ---------------- 3) chunk combine: 4 chunks/lane + warp Kogge-Stone --------------
// One warp per (b, n); lane handles chunks (4L .. 4L+3).
__global__ void scan_combine() {
    int t    = blockIdx.x * blockDim.x + threadIdx.x;   // 131072 threads = 4096 warps
    int lane = t & 31;
    int w    = t >> 5;
    int n    = w & (NN - 1);
    int b    = w >> 11;
    int base = (b * NCH + 4 * lane) * NN + n;
    float a0 = g_Aprod[base],          h0 = g_Hend[base];
    float a1 = g_Aprod[base + NN],     h1 = g_Hend[base + NN];
    float a2 = g_Aprod[base + 2 * NN], h2 = g_Hend[base + 2 * NN];
    float a3 = g_Aprod[base + 3 * NN], h3 = g_Hend[base + 3 * NN];
    float A01  = a1 * a0,  H01  = fmaf(a1, h0, h1);
    float A012 = a2 * A01, H012 = fmaf(a2, H01, h2);
    float A    = a3 * A012;
    float H    = fmaf(a3, H012, h3);
    #pragma unroll
    for (int d = 1; d < 32; d <<= 1) {
        float al = __shfl_up_sync(0xFFFFFFFFu, A, d);
        float hl = __shfl_up_sync(0xFFFFFFFFu, H, d);
        if (lane >= d) {
            H = fmaf(A, hl, H);
            A *= al;
        }
    }
    float hex = __shfl_up_sync(0xFFFFFFFFu, H, 1);      // exclusive over groups
    float hs = (lane == 0) ? 0.f : hex;
    g_Hstart[base]          = hs;
    g_Hstart[base + NN]     = fmaf(a0,   hs, h0);
    g_Hstart[base + 2 * NN] = fmaf(A01,  hs, H01);
    g_Hstart[base + 3 * NN] = fmaf(A012, hs, H012);
}

// ---------------- 4) scan pass 2: replay with correct h0, emit y (fp16) -----------
// 4-wide + 4-step batched prefetch (12 LDGs front-issued per block -> MLP ~12).
__global__ void scan_pass2() {
    int t  = blockIdx.x * blockDim.x + threadIdx.x;     // 131072 threads
    int n4 = (t & 511) << 2;
    int ch = (t >> 9) & (NCH - 1);
    int b  = t >> 16;
    int base = (b * SS + ch * LCH) * NN + n4;
    const float4* pa = (const float4*)(g_abar + base);
    const uint2*  pb = (const uint2*)(g_bbar2 + base);
    const uint2*  pc = (const uint2*)(g_cf2 + base);
    uint2* y = (uint2*)(g_y + base);
    float4 h = *(const float4*)&g_Hstart[(b * NCH + ch) * NN + n4];
    #pragma unroll
    for (int sb = 0; sb < LCH; sb += 4) {
        float4 av[4]; uint2 bv[4], cv[4];
        #pragma unroll
        for (int i = 0; i < 4; i++) {
            av[i] = pa[(sb + i) * (NN / 4)];
            bv[i] = pb[(sb + i) * (NN / 4)];
            cv[i] = pc[(sb + i) * (NN / 4)];
        }
        uint2 yv[4];
        #pragma unroll
        for (int i = 0; i < 4; i++) {
            union { uint2 u; __half2 b2[2]; } ub, uc, uy;
            ub.u = bv[i];
            uc.u = cv[i];
            float2 b0 = __half22float2(ub.b2[0]), b1 = __half22float2(ub.b2[1]);
            float2 c0 = __half22float2(uc.b2[0]), c1 = __half22float2(uc.b2[1]);
            h.x = fmaf(av[i].x, h.x, b0.x);
            h.y = fmaf(av[i].y, h.y, b0.y);
            h.z = fmaf(av[i].z, h.z, b1.x);
            h.w = fmaf(av[i].w, h.w, b1.y);
            uy.b2[0] = __floats2half2_rn(c0.x * h.x, c0.y * h.y);
            uy.b2[1] = __floats2half2_rn(c1.x * h.z, c1.y * h.w);
            yv[i] = uy.u;
        }
        #pragma unroll
        for (int i = 0; i < 4; i++)
            y[(sb + i) * (NN / 4)] = yv[i];
    }
}

// ---------------- 5) output projection GEMM + fused split-K reduction -------------
// out[m,d] = sum_n y[m,n] * W_out[d,n].  y and W_out single fp16 (1 pass).
// Block: 64 (m) x 128 (d), 512 K per block; last CTA of each m-block reduces.
#define G2_SY_ELEMS (2*64*40)
#define G2_SW_ELEMS (2*128*40)
#define G2_SMEM ((G2_SY_ELEMS + G2_SW_ELEMS) * 2)

__global__ __launch_bounds__(256, 2)
void gemm2_out(const float* __restrict__ bout, float* __restrict__ out) {
    extern __shared__ unsigned short smem2_u16[];
    typedef unsigned short (*SYt)[64][40];
    typedef unsigned short (*SWot)[128][40];
    SYt  sY  = (SYt)smem2_u16;
    SWot sWo = (SWot)(smem2_u16 + G2_SY_ELEMS);
    __shared__ int red;

    const int tid  = threadIdx.x;
    const int warp = tid >> 5, lane = tid & 31;
    const int wm = warp >> 2, wn = warp & 3;
    const int m0 = blockIdx.x * 64;
    const int kp = blockIdx.y;              // 0..3
    const int g  = lane >> 2, tg = lane & 3;
    const int lm = lane >> 3, lr = lane & 7;

    float acc[2][4][4];
    #pragma unroll
    for (int a = 0; a < 2; a++)
        #pragma unroll
        for (int b = 0; b < 4; b++)
            #pragma unroll
            for (int c = 0; c < 4; c++) acc[a][b][c] = 0.f;

    auto load_tiles = [&](int buf, int kc) {
        const int kbase = kp * 512 + kc * 32;
        {                                           // y: 256 x 16B
            int i = tid;
            int r = i >> 2, w = i & 3;
            const __half* src = g_y + (m0 + r) * NN + kbase + w * 8;
            cp16(&sY[buf][r][w * 8], src);
        }
        #pragma unroll
        for (int j = 0; j < 2; j++) {               // W_out: 512 x 16B
            int i = tid + j * 256;
            int r = (i >> 2) & 127, w = i & 3;
            const __half* src = g_Woh + r * NN + kbase + w * 8;
            cp16(&sWo[buf][r][w * 8], src);
        }
    };

    load_tiles(0, 0);
    CP_COMMIT();

    for (int kc = 0; kc < 16; kc++) {
        if (kc < 15) load_tiles((kc + 1) & 1, kc + 1);
        CP_COMMIT();
        CP_WAIT1();
        __syncthreads();
        const int buf = kc & 1;

        #pragma unroll
        for (int ks = 0; ks < 2; ks++) {
            const int kb = ks * 16;
            unsigned afr[2][4];
            #pragma unroll
            for (int mt = 0; mt < 2; mt++)
                ldsm4(afr[mt],
                      &sY[buf][wm * 32 + mt * 16 + (lm & 1) * 8 + lr][kb + (lm >> 1) * 8]);
            unsigned bfr[2][4];
            #pragma unroll
            for (int jp = 0; jp < 2; jp++)
                ldsm4(bfr[jp],
                      &sWo[buf][wn * 32 + (jp * 2 + (lm >> 1)) * 8 + lr][kb + (lm & 1) * 8]);

            #pragma unroll
            for (int nt = 0; nt < 4; nt++) {
                const unsigned* bp = &bfr[nt >> 1][(nt & 1) * 2];
                #pragma unroll
                for (int mt = 0; mt < 2; mt++)
                    mma_f16(acc[mt][nt], afr[mt], bp);
            }
        }
        __syncthreads();
    }

    // write deterministic split-K partials (float2 stores)
    float* part = g_part + kp * (MM * DD);
    #pragma unroll
    for (int mt = 0; mt < 2; mt++) {
        #pragma unroll
        for (int nt = 0; nt < 4; nt++) {
            int mr0 = m0 + wm * 32 + mt * 16 + g;
            int dc0 = wn * 32 + nt * 8 + tg * 2;
            #pragma unroll
            for (int half = 0; half < 2; half++) {
                int mr = mr0 + half * 8;
                float2 v;
                v.x = acc[mt][nt][half * 2 + 0];
                v.y = acc[mt][nt][half * 2 + 1];
                *(float2*)&part[mr * DD + dc0] = v;
            }
        }
    }

    // fused reduction: last CTA of this m-block sums the 4 partials + bias
    __threadfence();
    __syncthreads();
    if (tid == 0) red = atomicAdd(&g_cnt[blockIdx.x], 1);
    __syncthreads();
    if (red == 3) {
        const int MD = MM * DD;
        for (int j = tid; j < 64 * DD / 4; j += 256) {
            int idx = m0 * DD + j * 4;
            float4 v = *(const float4*)&bout[(j * 4) & (DD - 1)];
            float4 p0 = *(const float4*)&g_part[idx];
            float4 p1 = *(const float4*)&g_part[MD + idx];
            float4 p2 = *(const float4*)&g_part[2 * MD + idx];
            float4 p3 = *(const float4*)&g_part[3 * MD + idx];
            v.x += p0.x + p1.x + p2.x + p3.x;
            v.y += p0.y + p1.y + p2.y + p3.y;
            v.z += p0.z + p1.z + p2.z + p3.z;
            v.w += p0.w + p1.w + p2.w + p3.w;
            *(float4*)&out[idx] = v;
        }
        if (tid == 0) g_cnt[blockIdx.x] = 0;   // reset for next graph replay
    }
}

// ---------------- launch ----------------
extern "C" void kernel_launch(void* const* d_in, const int* in_sizes, int n_in,
                              void* d_out, int out_size) {
    const float* x     = (const float*)d_in[0];
    const float* W_B   = (const float*)d_in[1];
    const float* b_B   = (const float*)d_in[2];
    const float* W_C   = (const float*)d_in[3];
    const float* b_C   = (const float*)d_in[4];
    const float* W_dt  = (const float*)d_in[5];
    const float* b_dt  = (const float*)d_in[6];
    const float* A_log = (const float*)d_in[7];
    const float* W_out = (const float*)d_in[8];
    const float* b_out = (const float*)d_in[9];
    float* out = (float*)d_out;

    cudaFuncSetAttribute(gemm1_proj, cudaFuncAttributeMaxDynamicSharedMemorySize, G1_SMEM);
    cudaFuncSetAttribute(gemm2_out,  cudaFuncAttributeMaxDynamicSharedMemorySize, G2_SMEM);

    split_kernel<<<1536, 256>>>(x, W_B, W_C, W_dt, W_out);
    gemm1_proj<<<dim3(64, 32), 256, G1_SMEM>>>(b_B, b_C, b_dt, A_log);
    scan_combine<<<512, 256>>>();
    scan_pass2<<<512, 256>>>();
    gemm2_out<<<dim3(64, 4), 256, G2_SMEM>>>(b_out, out);
}